// round 2
// baseline (speedup 1.0000x reference)
#include <cuda_runtime.h>
#include <math.h>

// Problem constants
constexpr int S_ = 2048;
constexpr int B_ = 8;
constexpr int D_ = 1024;
constexpr int TCH = 256;           // chunk length (steps) for the chunked-scan approximation
constexpr int NCH = S_ / TCH;      // 8 chunks
constexpr int MC  = TCH * B_;      // 2048 rows per chunk
constexpr float LR_ = 1e-3f;

// Scratch (no cudaMalloc allowed)
static __device__ float g_K   [S_ * B_ * D_];   // [S,B,D] step-major keys
static __device__ float g_V   [S_ * B_ * D_];   // [S,B,D] step-major values
static __device__ float g_Q   [B_ * S_ * D_];   // queries (natural layout)
static __device__ float g_Hq  [B_ * S_ * D_];   // retrieve hidden
static __device__ float g_Pre [MC * D_];        // chunk pre-activation
static __device__ float g_H1  [MC * D_];        // chunk hidden
static __device__ float g_dY  [MC * D_];        // chunk dL/dY
static __device__ float g_dPre[MC * D_];        // chunk dL/dPre
static __device__ float g_W1  [D_ * D_];
static __device__ float g_W2  [D_ * D_];
static __device__ float g_b1  [D_];
static __device__ float g_b2  [D_];

__device__ __forceinline__ float sigf(float z) { return 1.f / (1.f + expf(-z)); }

enum {
    EPI_KV,        // scatter GEMM result to K/V in [S,B,D] layout
    EPI_PRE_SILU,  // store pre (C0) and silu(pre) (C1), bias added
    EPI_DY,        // C0 = scale * (acc + bias - aux)
    EPI_DPRE,      // C0 = acc * silu'(aux)
    EPI_SILU,      // C0 = silu(acc + bias)
    EPI_BIAS,      // C0 = acc (+ bias if non-null)
    EPI_UPDATE     // C0 -= scale * acc   (in-place weight update)
};

template <int BM, int BN, int BK, int TM, int TN, int TA, int TB, int EPI>
__global__ __launch_bounds__(256) void gemm_k(
    const float* __restrict__ A, const float* __restrict__ Bm,
    int M, int N, int K,
    const float* __restrict__ bias, const float* __restrict__ aux,
    float* __restrict__ C0, float* __restrict__ C1, float scale)
{
    __shared__ __align__(16) float As[BK][BM];
    __shared__ __align__(16) float Bs[BK][BN];

    const int tid = threadIdx.x;
    constexpr int TCX = BN / TN;            // threads along n
    const int tc = tid % TCX;
    const int tr = tid / TCX;
    const int m0 = blockIdx.y * BM;
    const int n0 = blockIdx.x * BN;
    const int lda = TA ? M : K;
    const int ldb = TB ? K : N;

    float acc[TM][TN];
#pragma unroll
    for (int u = 0; u < TM; u++)
#pragma unroll
        for (int v = 0; v < TN; v++) acc[u][v] = 0.f;

    for (int k0 = 0; k0 < K; k0 += BK) {
        for (int idx = tid; idx < BM * BK; idx += 256) {
            if (TA == 0) {
                int kk = idx % BK, i = idx / BK;
                As[kk][i] = A[(size_t)(m0 + i) * lda + (k0 + kk)];
            } else {
                int i = idx % BM, kk = idx / BM;
                As[kk][i] = A[(size_t)(k0 + kk) * lda + (m0 + i)];
            }
        }
        for (int idx = tid; idx < BN * BK; idx += 256) {
            if (TB == 0) {
                int j = idx % BN, kk = idx / BN;
                Bs[kk][j] = Bm[(size_t)(k0 + kk) * ldb + (n0 + j)];
            } else {
                int kk = idx % BK, j = idx / BK;
                Bs[kk][j] = Bm[(size_t)(n0 + j) * ldb + (k0 + kk)];
            }
        }
        __syncthreads();

#pragma unroll
        for (int kk = 0; kk < BK; kk++) {
            float ra[TM], rb[TN];
#pragma unroll
            for (int u = 0; u < TM; u += 4)
                *reinterpret_cast<float4*>(&ra[u]) =
                    *reinterpret_cast<const float4*>(&As[kk][tr * TM + u]);
#pragma unroll
            for (int v = 0; v < TN; v += 4)
                *reinterpret_cast<float4*>(&rb[v]) =
                    *reinterpret_cast<const float4*>(&Bs[kk][tc * TN + v]);
#pragma unroll
            for (int u = 0; u < TM; u++)
#pragma unroll
                for (int v = 0; v < TN; v++) acc[u][v] += ra[u] * rb[v];
        }
        __syncthreads();
    }

    // Epilogue
#pragma unroll
    for (int u = 0; u < TM; u++) {
        const int m = m0 + tr * TM + u;
#pragma unroll
        for (int v = 0; v < TN; v++) {
            const int n = n0 + tc * TN + v;
            float val = acc[u][v];
            if (EPI == EPI_KV) {
                int b = m >> 11;              // m = b*S + s
                int s = m & (S_ - 1);
                size_t dst = (size_t)(s * B_ + b) * D_;
                if (n < D_) C0[dst + n] = val;
                else        C1[dst + (n - D_)] = val;
            } else if (EPI == EPI_PRE_SILU) {
                val += bias[n];
                C0[(size_t)m * N + n] = val;
                C1[(size_t)m * N + n] = val * sigf(val);
            } else if (EPI == EPI_DY) {
                val += bias[n];
                C0[(size_t)m * N + n] = scale * (val - aux[(size_t)m * N + n]);
            } else if (EPI == EPI_DPRE) {
                float z = aux[(size_t)m * N + n];
                float sg = sigf(z);
                C0[(size_t)m * N + n] = val * (sg * (1.f + z * (1.f - sg)));
            } else if (EPI == EPI_SILU) {
                val += bias[n];
                C0[(size_t)m * N + n] = val * sigf(val);
            } else if (EPI == EPI_BIAS) {
                if (bias) val += bias[n];
                C0[(size_t)m * N + n] = val;
            } else if (EPI == EPI_UPDATE) {
                C0[(size_t)m * N + n] -= scale * val;
            }
        }
    }
}

// b -= lr * colsum(X[rows, D_])
__global__ void colsum_update(const float* __restrict__ X, int rows,
                              float* __restrict__ b, float lr)
{
    int col = blockIdx.x * 32 + threadIdx.x;
    float s = 0.f;
    for (int r = threadIdx.y; r < rows; r += 8)
        s += X[(size_t)r * D_ + col];
    __shared__ float sm[8][33];
    sm[threadIdx.y][threadIdx.x] = s;
    __syncthreads();
    if (threadIdx.y == 0) {
        float t = 0.f;
#pragma unroll
        for (int y = 0; y < 8; y++) t += sm[y][threadIdx.x];
        b[col] -= lr * t;
    }
}

struct ScratchPtrs {
    float *K, *V, *Q, *Hq, *Pre, *H1, *dY, *dPre, *W1, *W2, *b1, *b2;
};

static ScratchPtrs get_ptrs() {
    static ScratchPtrs p = [] {
        ScratchPtrs s{};
        cudaGetSymbolAddress((void**)&s.K,    g_K);
        cudaGetSymbolAddress((void**)&s.V,    g_V);
        cudaGetSymbolAddress((void**)&s.Q,    g_Q);
        cudaGetSymbolAddress((void**)&s.Hq,   g_Hq);
        cudaGetSymbolAddress((void**)&s.Pre,  g_Pre);
        cudaGetSymbolAddress((void**)&s.H1,   g_H1);
        cudaGetSymbolAddress((void**)&s.dY,   g_dY);
        cudaGetSymbolAddress((void**)&s.dPre, g_dPre);
        cudaGetSymbolAddress((void**)&s.W1,   g_W1);
        cudaGetSymbolAddress((void**)&s.W2,   g_W2);
        cudaGetSymbolAddress((void**)&s.b1,   g_b1);
        cudaGetSymbolAddress((void**)&s.b2,   g_b2);
        return s;
    }();
    return p;
}

extern "C" void kernel_launch(void* const* d_in, const int* in_sizes, int n_in,
                              void* d_out, int out_size)
{
    const float* x   = (const float*)d_in[0];
    const float* WQ  = (const float*)d_in[1];
    const float* WKV = (const float*)d_in[2];
    const float* W1i = (const float*)d_in[3];
    const float* b1i = (const float*)d_in[4];
    const float* W2i = (const float*)d_in[5];
    const float* b2i = (const float*)d_in[6];
    float* out = (float*)d_out;

    ScratchPtrs p = get_ptrs();

    // Fresh params every call (graph-replay deterministic)
    cudaMemcpyAsync(p.W1, W1i, (size_t)D_ * D_ * 4, cudaMemcpyDeviceToDevice);
    cudaMemcpyAsync(p.W2, W2i, (size_t)D_ * D_ * 4, cudaMemcpyDeviceToDevice);
    cudaMemcpyAsync(p.b1, b1i, (size_t)D_ * 4,      cudaMemcpyDeviceToDevice);
    cudaMemcpyAsync(p.b2, b2i, (size_t)D_ * 4,      cudaMemcpyDeviceToDevice);

    dim3 blk(256);
    const float c2 = 2.f / (float)(B_ * D_);

    // kv = x @ W_KV, scattered into step-major K/V
    gemm_k<128, 128, 8, 8, 8, 0, 0, EPI_KV>
        <<<dim3((2 * D_) / 128, (B_ * S_) / 128), blk>>>(
            x, WKV, B_ * S_, 2 * D_, D_, nullptr, nullptr, p.K, p.V, 0.f);

    // Chunked online-SGD scan
    for (int c = 0; c < NCH; c++) {
        const float* Kc = p.K + (size_t)c * MC * D_;
        const float* Vc = p.V + (size_t)c * MC * D_;
        // Pre = Kc@W1 + b1 ; H1 = silu(Pre)
        gemm_k<64, 64, 16, 4, 4, 0, 0, EPI_PRE_SILU>
            <<<dim3(D_ / 64, MC / 64), blk>>>(
                Kc, p.W1, MC, D_, D_, p.b1, nullptr, p.Pre, p.H1, 0.f);
        // dY = c2 * (H1@W2 + b2 - Vc)
        gemm_k<64, 64, 16, 4, 4, 0, 0, EPI_DY>
            <<<dim3(D_ / 64, MC / 64), blk>>>(
                p.H1, p.W2, MC, D_, D_, p.b2, Vc, p.dY, nullptr, c2);
        // dPre = (dY @ W2^T) * silu'(Pre)    -- uses old W2
        gemm_k<64, 64, 16, 4, 4, 0, 1, EPI_DPRE>
            <<<dim3(D_ / 64, MC / 64), blk>>>(
                p.dY, p.W2, MC, D_, D_, nullptr, p.Pre, p.dPre, nullptr, 0.f);
        // W2 -= LR * H1^T @ dY ; b2 -= LR * colsum(dY)
        gemm_k<64, 64, 16, 4, 4, 1, 0, EPI_UPDATE>
            <<<dim3(D_ / 64, D_ / 64), blk>>>(
                p.H1, p.dY, D_, D_, MC, nullptr, nullptr, p.W2, nullptr, LR_);
        colsum_update<<<D_ / 32, dim3(32, 8)>>>(p.dY, MC, p.b2, LR_);
        // W1 -= LR * Kc^T @ dPre ; b1 -= LR * colsum(dPre)
        gemm_k<64, 64, 16, 4, 4, 1, 0, EPI_UPDATE>
            <<<dim3(D_ / 64, D_ / 64), blk>>>(
                Kc, p.dPre, D_, D_, MC, nullptr, nullptr, p.W1, nullptr, LR_);
        colsum_update<<<D_ / 32, dim3(32, 8)>>>(p.dPre, MC, p.b1, LR_);
    }

    // Retrieve: out = silu(x@W_Q @ W1 + b1) @ W2 + b2
    gemm_k<128, 128, 8, 8, 8, 0, 0, EPI_BIAS>
        <<<dim3(D_ / 128, (B_ * S_) / 128), blk>>>(
            x, WQ, B_ * S_, D_, D_, nullptr, nullptr, p.Q, nullptr, 0.f);
    gemm_k<128, 128, 8, 8, 8, 0, 0, EPI_SILU>
        <<<dim3(D_ / 128, (B_ * S_) / 128), blk>>>(
            p.Q, p.W1, B_ * S_, D_, D_, p.b1, nullptr, p.Hq, nullptr, 0.f);
    gemm_k<128, 128, 8, 8, 8, 0, 0, EPI_BIAS>
        <<<dim3(D_ / 128, (B_ * S_) / 128), blk>>>(
            p.Hq, p.W2, B_ * S_, D_, D_, p.b2, nullptr, out, nullptr, 0.f);
}

// round 5
// speedup vs baseline: 2.6314x; 2.6314x over previous
#include <cuda_runtime.h>
#include <cuda_bf16.h>
#include <cstdint>

constexpr int S_ = 2048, B_ = 8, D_ = 1024;
constexpr int TCH = 256, NCH = S_ / TCH, MC = TCH * B_, SB = S_ * B_;
constexpr float LR_ = 1e-3f;
constexpr size_t E1 = (size_t)SB * D_;
constexpr size_t MCD = (size_t)MC * D_;
constexpr size_t DD = (size_t)D_ * D_;
constexpr size_t ARENA_BYTES = 460ull << 20;
static __device__ __align__(1024) unsigned char g_arena[ARENA_BYTES];
typedef __nv_bfloat16 bf;

// SMEM: 2 stages x 4 tiles(Ah,Al,Bh,Bl) x 128 rows x 80B pitch = 81920 B
constexpr int PITCH = 80;            // 32 bf16 (64B) + 16B pad -> conflict-free ldmatrix
constexpr int TILE_B = 128 * PITCH;  // 10240
constexpr int STAGE_B = 4 * TILE_B;  // 40960
constexpr int SMEM_SZ = 2 * STAGE_B; // 81920 (epilogue reuses: 128*132*4=67584 fits)

__device__ __forceinline__ uint32_t s2u(const void* p) {
    uint32_t a;
    asm("{ .reg .u64 t; cvta.to.shared.u64 t, %1; cvt.u32.u64 %0, t; }" : "=r"(a) : "l"(p));
    return a;
}
__device__ __forceinline__ void cpa16(uint32_t dst, const void* src) {
    asm volatile("cp.async.cg.shared.global [%0], [%1], 16;" :: "r"(dst), "l"(src));
}
__device__ __forceinline__ void ldsm4(uint32_t* r, uint32_t a) {
    asm volatile("ldmatrix.sync.aligned.m8n8.x4.shared.b16 {%0,%1,%2,%3}, [%4];"
                 : "=r"(r[0]), "=r"(r[1]), "=r"(r[2]), "=r"(r[3]) : "r"(a));
}
__device__ __forceinline__ void mma16816(float* c, const uint32_t* a, const uint32_t* b) {
    asm volatile("mma.sync.aligned.m16n8k16.row.col.f32.bf16.bf16.f32 "
                 "{%0,%1,%2,%3}, {%4,%5,%6,%7}, {%8,%9}, {%0,%1,%2,%3};"
                 : "+f"(c[0]), "+f"(c[1]), "+f"(c[2]), "+f"(c[3])
                 : "r"(a[0]), "r"(a[1]), "r"(a[2]), "r"(a[3]), "r"(b[0]), "r"(b[1]));
}
__device__ __forceinline__ float sigf(float z) { return 1.f / (1.f + __expf(-z)); }
__device__ __forceinline__ void hilo(float v, bf& h, bf& l) {
    h = __float2bfloat16(v); l = __float2bfloat16(v - __bfloat162float(h));
}
enum { EPI_KV, EPI_FWD, EPI_DY, EPI_DPRE, EPI_UPD, EPI_SILU, EPI_OUT, EPI_Q };

// issue one stage of cp.async loads (4 tiles of 128x32 bf16)
__device__ __forceinline__ void stage_load(
    uint32_t sbuf, const bf* Ah, const bf* Al, const bf* Bh, const bf* Bl,
    int m0, int n0, int K, int k0, int tid)
{
    const bf* gp[4] = { Ah, Al, Bh, Bl };
    const int r0[4] = { m0, m0, n0, n0 };
#pragma unroll
    for (int t = 0; t < 4; t++) {
#pragma unroll
        for (int i = 0; i < 2; i++) {
            int idx = tid + i * 256;          // 512 16B-chunks per tile
            int r = idx >> 2, c = idx & 3;
            cpa16(sbuf + t * TILE_B + r * PITCH + c * 16,
                  gp[t] + (size_t)(r0[t] + r) * K + k0 + c * 8);
        }
    }
    asm volatile("cp.async.commit_group;" ::: "memory");
}

// C[M,N] = A[M,K]*B[N,K]^T, split-bf16 (3 terms), grid=(N/128, M/128), 256 thr
template <int EPI>
__global__ __launch_bounds__(256) void gemm_tc(
    const bf* __restrict__ Ah, const bf* __restrict__ Al,
    const bf* __restrict__ Bh, const bf* __restrict__ Bl,
    int K, int Nout, const float* __restrict__ bias, const float* __restrict__ aux,
    float* __restrict__ f0, bf* __restrict__ oh, bf* __restrict__ ol, float scale)
{
    extern __shared__ __align__(128) char smem[];
    const uint32_t sbase = s2u(smem);
    const int tid = threadIdx.x, lane = tid & 31, wid = tid >> 5;
    const int warp_m = wid & 1, warp_n = wid >> 1;      // 2 x 4 warps
    const int m0 = blockIdx.y * 128, n0 = blockIdx.x * 128;

    float acc[4][4][4];
#pragma unroll
    for (int a = 0; a < 4; a++)
#pragma unroll
        for (int b = 0; b < 4; b++)
#pragma unroll
            for (int e = 0; e < 4; e++) acc[a][b][e] = 0.f;

    const int nst = K >> 5;
    stage_load(sbase, Ah, Al, Bh, Bl, m0, n0, K, 0, tid);

    for (int s = 0; s < nst; s++) {
        if (s + 1 < nst) {
            stage_load(sbase + ((s + 1) & 1) * STAGE_B, Ah, Al, Bh, Bl,
                       m0, n0, K, (s + 1) * 32, tid);
            asm volatile("cp.async.wait_group 1;" ::: "memory");
        } else {
            asm volatile("cp.async.wait_group 0;" ::: "memory");
        }
        __syncthreads();
        const uint32_t st = sbase + (s & 1) * STAGE_B;
        const uint32_t sAh = st, sAl = st + TILE_B, sBh = st + 2 * TILE_B, sBl = st + 3 * TILE_B;

#pragma unroll
        for (int kc = 0; kc < 2; kc++) {
            uint32_t ra[4][4], rl[4][4], bh2[4][2], bl2[4][2];
            const uint32_t a_off = kc * 32 + (lane >> 4) * 16;
            const int arow = warp_m * 64 + (lane & 15);
#pragma unroll
            for (int mt = 0; mt < 4; mt++) {
                ldsm4(ra[mt], sAh + (arow + mt * 16) * PITCH + a_off);
                ldsm4(rl[mt], sAl + (arow + mt * 16) * PITCH + a_off);
            }
            const int browoff = ((lane >> 4) << 3) + (lane & 7);
            const uint32_t b_off = kc * 32 + (((lane >> 3) & 1) * 16);
#pragma unroll
            for (int np = 0; np < 2; np++) {
                uint32_t r4[4];
                ldsm4(r4, sBh + (warp_n * 32 + np * 16 + browoff) * PITCH + b_off);
                bh2[2*np][0] = r4[0]; bh2[2*np][1] = r4[1];
                bh2[2*np+1][0] = r4[2]; bh2[2*np+1][1] = r4[3];
                ldsm4(r4, sBl + (warp_n * 32 + np * 16 + browoff) * PITCH + b_off);
                bl2[2*np][0] = r4[0]; bl2[2*np][1] = r4[1];
                bl2[2*np+1][0] = r4[2]; bl2[2*np+1][1] = r4[3];
            }
#pragma unroll
            for (int mt = 0; mt < 4; mt++)
#pragma unroll
                for (int nt = 0; nt < 4; nt++) {
                    mma16816(acc[mt][nt], ra[mt], bh2[nt]);
                    mma16816(acc[mt][nt], ra[mt], bl2[nt]);
                    mma16816(acc[mt][nt], rl[mt], bh2[nt]);
                }
        }
        __syncthreads();
    }

    // stage accumulators to smem (pitch 132 floats)
    float* stg = reinterpret_cast<float*>(smem);
    {
        const int rb = warp_m * 64 + (lane >> 2);
        const int cb = warp_n * 32 + (lane & 3) * 2;
#pragma unroll
        for (int mt = 0; mt < 4; mt++)
#pragma unroll
            for (int nt = 0; nt < 4; nt++) {
                const int r = rb + mt * 16, c = cb + nt * 8;
                stg[r * 132 + c]           = acc[mt][nt][0];
                stg[r * 132 + c + 1]       = acc[mt][nt][1];
                stg[(r + 8) * 132 + c]     = acc[mt][nt][2];
                stg[(r + 8) * 132 + c + 1] = acc[mt][nt][3];
            }
    }
    __syncthreads();

    // coalesced fused epilogue
    const int row = tid >> 1, col0 = (tid & 1) * 64;
    const int m = m0 + row;
#pragma unroll 4
    for (int j = 0; j < 64; j += 4) {
        float4 v4 = *reinterpret_cast<float4*>(&stg[row * 132 + col0 + j]);
        float vv[4] = { v4.x, v4.y, v4.z, v4.w };
#pragma unroll
        for (int e = 0; e < 4; e++) {
            const int n = n0 + col0 + j + e;
            float v = vv[e];
            if (EPI == EPI_KV) {
                const int bb = m >> 11, ss = m & (S_ - 1);
                const size_t base = (size_t)(ss * B_ + bb) * D_;
                if (n < D_) { bf h, l; hilo(v, h, l); oh[base + n] = h; ol[base + n] = l; }
                else f0[base + n - D_] = v;
            } else if (EPI == EPI_FWD) {
                const float pre = v + bias[n];
                f0[(size_t)m * Nout + n] = pre;
                bf h, l; hilo(pre * sigf(pre), h, l);
                oh[(size_t)m * Nout + n] = h; ol[(size_t)m * Nout + n] = l;
            } else if (EPI == EPI_DY) {
                const float d = scale * (v + bias[n] - aux[(size_t)m * Nout + n]);
                bf h, l; hilo(d, h, l);
                oh[(size_t)m * Nout + n] = h; ol[(size_t)m * Nout + n] = l;
            } else if (EPI == EPI_DPRE) {
                const float z = aux[(size_t)m * Nout + n], sg = sigf(z);
                bf h, l; hilo(v * (sg * (1.f + z * (1.f - sg))), h, l);
                oh[(size_t)m * Nout + n] = h; ol[(size_t)m * Nout + n] = l;
            } else if (EPI == EPI_UPD) {
                f0[(size_t)m * Nout + n] -= scale * v;
            } else if (EPI == EPI_SILU) {
                const float pre = v + bias[n];
                bf h, l; hilo(pre * sigf(pre), h, l);
                oh[(size_t)m * Nout + n] = h; ol[(size_t)m * Nout + n] = l;
            } else if (EPI == EPI_OUT) {
                f0[(size_t)m * Nout + n] = v + bias[n];
            } else {  // EPI_Q
                bf h, l; hilo(v, h, l);
                oh[(size_t)m * Nout + n] = h; ol[(size_t)m * Nout + n] = l;
            }
        }
    }
}

__global__ __launch_bounds__(256) void conv_x(const float* __restrict__ in,
                                              bf* __restrict__ oh, bf* __restrict__ ol) {
    size_t i = (size_t)blockIdx.x * 1024 + threadIdx.x * 4;
    float4 v = *reinterpret_cast<const float4*>(in + i);
    bf h, l;
    hilo(v.x, h, l); oh[i] = h;   ol[i] = l;
    hilo(v.y, h, l); oh[i+1] = h; ol[i+1] = l;
    hilo(v.z, h, l); oh[i+2] = h; ol[i+2] = l;
    hilo(v.w, h, l); oh[i+3] = h; ol[i+3] = l;
}
__global__ void tconv(const float* __restrict__ W, int R, int C,
                      bf* __restrict__ Th, bf* __restrict__ Tl,
                      bf* __restrict__ Nh, bf* __restrict__ Nl) {
    __shared__ float t[32][33];
    const int c0 = blockIdx.x * 32, r0 = blockIdx.y * 32, tx = threadIdx.x;
    for (int i = threadIdx.y; i < 32; i += 8) {
        float v = W[(size_t)(r0 + i) * C + c0 + tx];
        t[i][tx] = v;
        if (Nh) { bf h, l; hilo(v, h, l);
            Nh[(size_t)(r0 + i) * C + c0 + tx] = h; Nl[(size_t)(r0 + i) * C + c0 + tx] = l; }
    }
    __syncthreads();
    for (int i = threadIdx.y; i < 32; i += 8) {
        bf h, l; hilo(t[tx][i], h, l);
        Th[(size_t)(c0 + i) * R + r0 + tx] = h; Tl[(size_t)(c0 + i) * R + r0 + tx] = l;
    }
}
__global__ void tbf16(const bf* __restrict__ ih, const bf* __restrict__ il, int R, int C,
                      bf* __restrict__ oh, bf* __restrict__ ol) {
    __shared__ bf th[32][33], tl[32][33];
    const int c0 = blockIdx.x * 32, r0 = blockIdx.y * 32, tx = threadIdx.x;
    for (int i = threadIdx.y; i < 32; i += 8) {
        th[i][tx] = ih[(size_t)(r0 + i) * C + c0 + tx];
        tl[i][tx] = il[(size_t)(r0 + i) * C + c0 + tx];
    }
    __syncthreads();
    for (int i = threadIdx.y; i < 32; i += 8) {
        oh[(size_t)(c0 + i) * R + r0 + tx] = th[tx][i];
        ol[(size_t)(c0 + i) * R + r0 + tx] = tl[tx][i];
    }
}
__global__ void colsum(const bf* __restrict__ h, const bf* __restrict__ l, int rows,
                       float* __restrict__ b, float lr) {
    int col = blockIdx.x * 32 + threadIdx.x;
    float s = 0.f;
    for (int r = threadIdx.y; r < rows; r += 8)
        s += __bfloat162float(h[(size_t)r * D_ + col]) + __bfloat162float(l[(size_t)r * D_ + col]);
    __shared__ float sm[8][33];
    sm[threadIdx.y][threadIdx.x] = s;
    __syncthreads();
    if (threadIdx.y == 0) {
        float t = 0.f;
#pragma unroll
        for (int y = 0; y < 8; y++) t += sm[y][threadIdx.x];
        b[col] -= lr * t;
    }
}

struct P_ {
    bf *xh, *xl, *Kh, *Kl, *Qh, *Ql, *Hqh, *Hql;
    float *V, *Pre, *W1, *W2, *b1, *b2;
    bf *H1h, *H1l, *dYh, *dYl, *dPh, *dPl;
    bf *H1th, *H1tl, *dYth, *dYtl, *dPth, *dPtl, *Kth, *Ktl;
    bf *W1Th, *W1Tl, *W2Th, *W2Tl, *W2h, *W2l, *WQTh, *WQTl, *WKVTh, *WKVTl;
};
static P_ getp() {
    static P_ p = [] {
        P_ s{};
        unsigned char* a;
        cudaGetSymbolAddress((void**)&a, g_arena);
        auto al = [&](size_t bytes) { unsigned char* r = a; a += (bytes + 1023) & ~1023ull; return r; };
        s.xh=(bf*)al(E1*2); s.xl=(bf*)al(E1*2); s.Kh=(bf*)al(E1*2); s.Kl=(bf*)al(E1*2);
        s.Qh=(bf*)al(E1*2); s.Ql=(bf*)al(E1*2); s.Hqh=(bf*)al(E1*2); s.Hql=(bf*)al(E1*2);
        s.V=(float*)al(E1*4); s.Pre=(float*)al(MCD*4);
        s.W1=(float*)al(DD*4); s.W2=(float*)al(DD*4); s.b1=(float*)al(D_*4); s.b2=(float*)al(D_*4);
        s.H1h=(bf*)al(MCD*2); s.H1l=(bf*)al(MCD*2); s.dYh=(bf*)al(MCD*2); s.dYl=(bf*)al(MCD*2);
        s.dPh=(bf*)al(MCD*2); s.dPl=(bf*)al(MCD*2);
        s.H1th=(bf*)al(MCD*2); s.H1tl=(bf*)al(MCD*2); s.dYth=(bf*)al(MCD*2); s.dYtl=(bf*)al(MCD*2);
        s.dPth=(bf*)al(MCD*2); s.dPtl=(bf*)al(MCD*2); s.Kth=(bf*)al(MCD*2); s.Ktl=(bf*)al(MCD*2);
        s.W1Th=(bf*)al(DD*2); s.W1Tl=(bf*)al(DD*2); s.W2Th=(bf*)al(DD*2); s.W2Tl=(bf*)al(DD*2);
        s.W2h=(bf*)al(DD*2); s.W2l=(bf*)al(DD*2); s.WQTh=(bf*)al(DD*2); s.WQTl=(bf*)al(DD*2);
        s.WKVTh=(bf*)al(DD*4); s.WKVTl=(bf*)al(DD*4);
        cudaFuncSetAttribute(gemm_tc<EPI_KV>,   cudaFuncAttributeMaxDynamicSharedMemorySize, SMEM_SZ);
        cudaFuncSetAttribute(gemm_tc<EPI_FWD>,  cudaFuncAttributeMaxDynamicSharedMemorySize, SMEM_SZ);
        cudaFuncSetAttribute(gemm_tc<EPI_DY>,   cudaFuncAttributeMaxDynamicSharedMemorySize, SMEM_SZ);
        cudaFuncSetAttribute(gemm_tc<EPI_DPRE>, cudaFuncAttributeMaxDynamicSharedMemorySize, SMEM_SZ);
        cudaFuncSetAttribute(gemm_tc<EPI_UPD>,  cudaFuncAttributeMaxDynamicSharedMemorySize, SMEM_SZ);
        cudaFuncSetAttribute(gemm_tc<EPI_SILU>, cudaFuncAttributeMaxDynamicSharedMemorySize, SMEM_SZ);
        cudaFuncSetAttribute(gemm_tc<EPI_OUT>,  cudaFuncAttributeMaxDynamicSharedMemorySize, SMEM_SZ);
        cudaFuncSetAttribute(gemm_tc<EPI_Q>,    cudaFuncAttributeMaxDynamicSharedMemorySize, SMEM_SZ);
        return s;
    }();
    return p;
}

extern "C" void kernel_launch(void* const* d_in, const int* in_sizes, int n_in,
                              void* d_out, int out_size)
{
    const float* x   = (const float*)d_in[0];
    const float* WQ  = (const float*)d_in[1];
    const float* WKV = (const float*)d_in[2];
    const float* W1i = (const float*)d_in[3];
    const float* b1i = (const float*)d_in[4];
    const float* W2i = (const float*)d_in[5];
    const float* b2i = (const float*)d_in[6];
    float* out = (float*)d_out;
    P_ p = getp();
    const dim3 t8(32, 8);
    const float c2 = 2.f / (float)(B_ * D_);

    cudaMemcpyAsync(p.W1, W1i, DD * 4, cudaMemcpyDeviceToDevice);
    cudaMemcpyAsync(p.W2, W2i, DD * 4, cudaMemcpyDeviceToDevice);
    cudaMemcpyAsync(p.b1, b1i, D_ * 4, cudaMemcpyDeviceToDevice);
    cudaMemcpyAsync(p.b2, b2i, D_ * 4, cudaMemcpyDeviceToDevice);

    conv_x<<<E1 / 1024, 256>>>(x, p.xh, p.xl);
    tconv<<<dim3(32, 32), t8>>>(WQ, D_, D_, p.WQTh, p.WQTl, nullptr, nullptr);
    tconv<<<dim3(64, 32), t8>>>(WKV, D_, 2 * D_, p.WKVTh, p.WKVTl, nullptr, nullptr);
    tconv<<<dim3(32, 32), t8>>>(p.W1, D_, D_, p.W1Th, p.W1Tl, nullptr, nullptr);
    tconv<<<dim3(32, 32), t8>>>(p.W2, D_, D_, p.W2Th, p.W2Tl, p.W2h, p.W2l);

    // kv = x @ W_KV  -> K hi/lo + V fp32, step-major
    gemm_tc<EPI_KV><<<dim3(16, 128), 256, SMEM_SZ>>>(
        p.xh, p.xl, p.WKVTh, p.WKVTl, D_, 2 * D_, nullptr, nullptr, p.V, p.Kh, p.Kl, 0.f);

    for (int c = 0; c < NCH; c++) {
        const bf* Kch = p.Kh + (size_t)c * MCD;
        const bf* Kcl = p.Kl + (size_t)c * MCD;
        const float* Vc = p.V + (size_t)c * MCD;
        gemm_tc<EPI_FWD><<<dim3(8, 16), 256, SMEM_SZ>>>(
            Kch, Kcl, p.W1Th, p.W1Tl, D_, D_, p.b1, nullptr, p.Pre, p.H1h, p.H1l, 0.f);
        gemm_tc<EPI_DY><<<dim3(8, 16), 256, SMEM_SZ>>>(
            p.H1h, p.H1l, p.W2Th, p.W2Tl, D_, D_, p.b2, Vc, nullptr, p.dYh, p.dYl, c2);
        gemm_tc<EPI_DPRE><<<dim3(8, 16), 256, SMEM_SZ>>>(
            p.dYh, p.dYl, p.W2h, p.W2l, D_, D_, nullptr, p.Pre, nullptr, p.dPh, p.dPl, 0.f);
        tbf16<<<dim3(32, 64), t8>>>(p.H1h, p.H1l, MC, D_, p.H1th, p.H1tl);
        tbf16<<<dim3(32, 64), t8>>>(p.dYh, p.dYl, MC, D_, p.dYth, p.dYtl);
        tbf16<<<dim3(32, 64), t8>>>(p.dPh, p.dPl, MC, D_, p.dPth, p.dPtl);
        tbf16<<<dim3(32, 64), t8>>>(Kch, Kcl, MC, D_, p.Kth, p.Ktl);
        gemm_tc<EPI_UPD><<<dim3(8, 8), 256, SMEM_SZ>>>(
            p.H1th, p.H1tl, p.dYth, p.dYtl, MC, D_, nullptr, nullptr, p.W2, nullptr, nullptr, LR_);
        colsum<<<32, t8>>>(p.dYh, p.dYl, MC, p.b2, LR_);
        gemm_tc<EPI_UPD><<<dim3(8, 8), 256, SMEM_SZ>>>(
            p.Kth, p.Ktl, p.dPth, p.dPtl, MC, D_, nullptr, nullptr, p.W1, nullptr, nullptr, LR_);
        colsum<<<32, t8>>>(p.dPh, p.dPl, MC, p.b1, LR_);
        tconv<<<dim3(32, 32), t8>>>(p.W2, D_, D_, p.W2Th, p.W2Tl, p.W2h, p.W2l);
        tconv<<<dim3(32, 32), t8>>>(p.W1, D_, D_, p.W1Th, p.W1Tl, nullptr, nullptr);
    }

    gemm_tc<EPI_Q><<<dim3(8, 128), 256, SMEM_SZ>>>(
        p.xh, p.xl, p.WQTh, p.WQTl, D_, D_, nullptr, nullptr, nullptr, p.Qh, p.Ql, 0.f);
    gemm_tc<EPI_SILU><<<dim3(8, 128), 256, SMEM_SZ>>>(
        p.Qh, p.Ql, p.W1Th, p.W1Tl, D_, D_, p.b1, nullptr, nullptr, p.Hqh, p.Hql, 0.f);
    gemm_tc<EPI_OUT><<<dim3(8, 128), 256, SMEM_SZ>>>(
        p.Hqh, p.Hql, p.W2Th, p.W2Tl, D_, D_, p.b2, nullptr, out, nullptr, nullptr, 0.f);
}

// round 8
// speedup vs baseline: 3.5832x; 1.3617x over previous
#include <cuda_runtime.h>
#include <cuda_bf16.h>
#include <cstdint>

constexpr int S_ = 2048, B_ = 8, D_ = 1024;
constexpr int TCH = 256, NCH = S_ / TCH, MC = TCH * B_, SB = S_ * B_;
constexpr float LR_ = 1e-3f;
constexpr size_t E1 = (size_t)SB * D_;
constexpr size_t MCD = (size_t)MC * D_;
constexpr size_t DD = (size_t)D_ * D_;
constexpr size_t ARENA_BYTES = 460ull << 20;
static __device__ __align__(1024) unsigned char g_arena[ARENA_BYTES];
typedef __nv_bfloat16 bf;

constexpr int PITCH = 80;            // 32 bf16 + 16B pad
constexpr int TILE_B = 128 * PITCH;
constexpr int STAGE_B = 4 * TILE_B;  // 40960
constexpr int SMEM_SZ = 2 * STAGE_B; // 81920; 2 CTAs/SM -> 160KB < 227KB

__device__ __forceinline__ uint32_t s2u(const void* p) {
    uint32_t a;
    asm("{ .reg .u64 t; cvta.to.shared.u64 t, %1; cvt.u32.u64 %0, t; }" : "=r"(a) : "l"(p));
    return a;
}
__device__ __forceinline__ void cpa16(uint32_t dst, const void* src) {
    asm volatile("cp.async.cg.shared.global [%0], [%1], 16;" :: "r"(dst), "l"(src));
}
__device__ __forceinline__ void ldsm4(uint32_t* r, uint32_t a) {
    asm volatile("ldmatrix.sync.aligned.m8n8.x4.shared.b16 {%0,%1,%2,%3}, [%4];"
                 : "=r"(r[0]), "=r"(r[1]), "=r"(r[2]), "=r"(r[3]) : "r"(a));
}
__device__ __forceinline__ void mma16816(float* c, const uint32_t* a, const uint32_t* b) {
    asm volatile("mma.sync.aligned.m16n8k16.row.col.f32.bf16.bf16.f32 "
                 "{%0,%1,%2,%3}, {%4,%5,%6,%7}, {%8,%9}, {%0,%1,%2,%3};"
                 : "+f"(c[0]), "+f"(c[1]), "+f"(c[2]), "+f"(c[3])
                 : "r"(a[0]), "r"(a[1]), "r"(a[2]), "r"(a[3]), "r"(b[0]), "r"(b[1]));
}
__device__ __forceinline__ float sigf(float z) { return 1.f / (1.f + __expf(-z)); }
__device__ __forceinline__ void hilo(float v, bf& h, bf& l) {
    h = __float2bfloat16(v); l = __float2bfloat16(v - __bfloat162float(h));
}
enum { EPI_KV, EPI_FWD, EPI_DY, EPI_DPRE, EPI_UPD, EPI_SILU, EPI_OUT, EPI_Q };

__device__ __forceinline__ void stage_load(
    uint32_t sbuf, const bf* Ah, const bf* Al, const bf* Bh, const bf* Bl,
    int m0, int n0, int K, int k0, int tid)
{
    const bf* gp[4] = { Ah, Al, Bh, Bl };
    const int r0[4] = { m0, m0, n0, n0 };
#pragma unroll
    for (int t = 0; t < 4; t++)
#pragma unroll
        for (int i = 0; i < 2; i++) {
            int idx = tid + i * 256;
            int r = idx >> 2, c = idx & 3;
            cpa16(sbuf + t * TILE_B + r * PITCH + c * 16,
                  gp[t] + (size_t)(r0[t] + r) * K + k0 + c * 8);
        }
    asm volatile("cp.async.commit_group;" ::: "memory");
}

// C[M,N] = A[M,K]*B[N,K]^T, split-bf16 (3 terms), grid=(N/128, M/128)
template <int EPI, bool OT>
__global__ __launch_bounds__(256, 2) void gemm_tc(
    const bf* __restrict__ Ah, const bf* __restrict__ Al,
    const bf* __restrict__ Bh, const bf* __restrict__ Bl,
    int K, int Nout, int mtot,
    const float* __restrict__ bias, const float* __restrict__ aux,
    float* __restrict__ f0, bf* __restrict__ oh, bf* __restrict__ ol,
    bf* __restrict__ oth, bf* __restrict__ otl, float scale)
{
    extern __shared__ __align__(128) char smem[];
    const uint32_t sbase = s2u(smem);
    const int tid = threadIdx.x, lane = tid & 31, wid = tid >> 5;
    const int warp_m = wid & 1, warp_n = wid >> 1;
    const int m0 = blockIdx.y * 128, n0 = blockIdx.x * 128;

    float acc[4][4][4];
#pragma unroll
    for (int a = 0; a < 4; a++)
#pragma unroll
        for (int b = 0; b < 4; b++)
#pragma unroll
            for (int e = 0; e < 4; e++) acc[a][b][e] = 0.f;

    const int nst = K >> 5;
    stage_load(sbase, Ah, Al, Bh, Bl, m0, n0, K, 0, tid);

    for (int s = 0; s < nst; s++) {
        if (s + 1 < nst) {
            stage_load(sbase + ((s + 1) & 1) * STAGE_B, Ah, Al, Bh, Bl,
                       m0, n0, K, (s + 1) * 32, tid);
            asm volatile("cp.async.wait_group 1;" ::: "memory");
        } else {
            asm volatile("cp.async.wait_group 0;" ::: "memory");
        }
        __syncthreads();
        const uint32_t st = sbase + (s & 1) * STAGE_B;
        const uint32_t sAh = st, sAl = st + TILE_B, sBh = st + 2 * TILE_B, sBl = st + 3 * TILE_B;

#pragma unroll
        for (int kc = 0; kc < 2; kc++) {
            uint32_t ra[4][4], rl[4][4];
            const uint32_t a_off = kc * 32 + (lane >> 4) * 16;
            const int arow = warp_m * 64 + (lane & 15);
#pragma unroll
            for (int mt = 0; mt < 4; mt++) {
                ldsm4(ra[mt], sAh + (arow + mt * 16) * PITCH + a_off);
                ldsm4(rl[mt], sAl + (arow + mt * 16) * PITCH + a_off);
            }
            const int browoff = ((lane >> 4) << 3) + (lane & 7);
            const uint32_t b_off = kc * 32 + (((lane >> 3) & 1) * 16);
#pragma unroll
            for (int np = 0; np < 2; np++) {
                uint32_t r4h[4], r4l[4];
                ldsm4(r4h, sBh + (warp_n * 32 + np * 16 + browoff) * PITCH + b_off);
                ldsm4(r4l, sBl + (warp_n * 32 + np * 16 + browoff) * PITCH + b_off);
#pragma unroll
                for (int hf = 0; hf < 2; hf++) {
                    const int nt = 2 * np + hf;
                    uint32_t bh2[2] = { r4h[2 * hf], r4h[2 * hf + 1] };
                    uint32_t bl2[2] = { r4l[2 * hf], r4l[2 * hf + 1] };
#pragma unroll
                    for (int mt = 0; mt < 4; mt++) {
                        mma16816(acc[mt][nt], ra[mt], bh2);
                        mma16816(acc[mt][nt], ra[mt], bl2);
                        mma16816(acc[mt][nt], rl[mt], bh2);
                    }
                }
            }
        }
        __syncthreads();
    }

    float* stg = reinterpret_cast<float*>(smem);
    {
        const int rb = warp_m * 64 + (lane >> 2);
        const int cb = warp_n * 32 + (lane & 3) * 2;
#pragma unroll
        for (int mt = 0; mt < 4; mt++)
#pragma unroll
            for (int nt = 0; nt < 4; nt++) {
                const int r = rb + mt * 16, c = cb + nt * 8;
                stg[r * 132 + c]           = acc[mt][nt][0];
                stg[r * 132 + c + 1]       = acc[mt][nt][1];
                stg[(r + 8) * 132 + c]     = acc[mt][nt][2];
                stg[(r + 8) * 132 + c + 1] = acc[mt][nt][3];
            }
    }
    __syncthreads();

    // normal pass (writes finals back into stage for the transposed pass)
    const int row = tid >> 1, col0 = (tid & 1) * 64;
    const int m = m0 + row;
#pragma unroll 2
    for (int j = 0; j < 64; j += 4) {
        float4 v4 = *reinterpret_cast<float4*>(&stg[row * 132 + col0 + j]);
        float vv[4] = { v4.x, v4.y, v4.z, v4.w };
        float fin[4];
        const int nb = n0 + col0 + j;
        if (EPI == EPI_KV) {
            const int bb = m >> 11, ss = m & (S_ - 1);
            const size_t base = (size_t)(ss * B_ + bb) * D_;
            if (nb < D_) {
                bf h[4], l[4];
#pragma unroll
                for (int e = 0; e < 4; e++) hilo(vv[e], h[e], l[e]);
                *reinterpret_cast<uint2*>(oh + base + nb) = *reinterpret_cast<uint2*>(h);
                *reinterpret_cast<uint2*>(ol + base + nb) = *reinterpret_cast<uint2*>(l);
            } else {
                *reinterpret_cast<float4*>(f0 + base + nb - D_) = v4;
            }
            continue;
        }
#pragma unroll
        for (int e = 0; e < 4; e++) {
            const int n = nb + e;
            const float v = vv[e];
            if (EPI == EPI_FWD) {
                const float pre = v + bias[n];
                fin[e] = pre * sigf(pre);
            } else if (EPI == EPI_DY) {
                fin[e] = scale * (v + bias[n] - aux[(size_t)m * Nout + n]);
            } else if (EPI == EPI_DPRE) {
                const float z = aux[(size_t)m * Nout + n], sg = sigf(z);
                fin[e] = v * (sg * (1.f + z * (1.f - sg)));
            } else if (EPI == EPI_UPD) {
                fin[e] = f0[(size_t)m * Nout + n] - scale * v;
            } else if (EPI == EPI_SILU) {
                const float pre = v + bias[n];
                fin[e] = pre * sigf(pre);
            } else if (EPI == EPI_OUT) {
                fin[e] = v + bias[n];
            } else {  // EPI_Q
                fin[e] = v;
            }
        }
        if (EPI == EPI_FWD) {  // Pre
            float4 pr; pr.x = vv[0] + bias[nb]; pr.y = vv[1] + bias[nb+1];
            pr.z = vv[2] + bias[nb+2]; pr.w = vv[3] + bias[nb+3];
            *reinterpret_cast<float4*>(f0 + (size_t)m * Nout + nb) = pr;
        }
        if (EPI == EPI_UPD || EPI == EPI_OUT) {
            float4 w; w.x = fin[0]; w.y = fin[1]; w.z = fin[2]; w.w = fin[3];
            *reinterpret_cast<float4*>(f0 + (size_t)m * Nout + nb) = w;
        }
        if (oh) {
            bf h[4], l[4];
#pragma unroll
            for (int e = 0; e < 4; e++) hilo(fin[e], h[e], l[e]);
            *reinterpret_cast<uint2*>(oh + (size_t)m * Nout + nb) = *reinterpret_cast<uint2*>(h);
            *reinterpret_cast<uint2*>(ol + (size_t)m * Nout + nb) = *reinterpret_cast<uint2*>(l);
        }
        if (OT) *reinterpret_cast<float4*>(&stg[row * 132 + col0 + j]) =
                    make_float4(fin[0], fin[1], fin[2], fin[3]);
    }

    if (OT) {
        __syncthreads();
        const int nrow = tid >> 1, mc0 = (tid & 1) * 64;
        const size_t gn = (size_t)(n0 + nrow);
#pragma unroll 2
        for (int j0 = 0; j0 < 64; j0 += 8) {
            union { bf b[8]; uint4 u; } H, L;
#pragma unroll
            for (int j = 0; j < 8; j++)
                hilo(stg[(mc0 + j0 + j) * 132 + nrow], H.b[j], L.b[j]);
            const size_t addr = gn * mtot + (m0 + mc0 + j0);
            *reinterpret_cast<uint4*>(oth + addr) = H.u;
            *reinterpret_cast<uint4*>(otl + addr) = L.u;
        }
    }
}

__global__ __launch_bounds__(256) void conv_x(const float* __restrict__ in,
                                              bf* __restrict__ oh, bf* __restrict__ ol) {
    size_t i = (size_t)blockIdx.x * 1024 + threadIdx.x * 4;
    float4 v = *reinterpret_cast<const float4*>(in + i);
    bf h[4], l[4];
    hilo(v.x, h[0], l[0]); hilo(v.y, h[1], l[1]);
    hilo(v.z, h[2], l[2]); hilo(v.w, h[3], l[3]);
    *reinterpret_cast<uint2*>(oh + i) = *reinterpret_cast<uint2*>(h);
    *reinterpret_cast<uint2*>(ol + i) = *reinterpret_cast<uint2*>(l);
}
__global__ void tconv(const float* __restrict__ W, int R, int C,
                      bf* __restrict__ Th, bf* __restrict__ Tl,
                      bf* __restrict__ Nh, bf* __restrict__ Nl) {
    __shared__ float t[32][33];
    const int c0 = blockIdx.x * 32, r0 = blockIdx.y * 32, tx = threadIdx.x;
    for (int i = threadIdx.y; i < 32; i += 8) {
        float v = W[(size_t)(r0 + i) * C + c0 + tx];
        t[i][tx] = v;
        if (Nh) { bf h, l; hilo(v, h, l);
            Nh[(size_t)(r0 + i) * C + c0 + tx] = h; Nl[(size_t)(r0 + i) * C + c0 + tx] = l; }
    }
    __syncthreads();
    for (int i = threadIdx.y; i < 32; i += 8) {
        bf h, l; hilo(t[tx][i], h, l);
        Th[(size_t)(c0 + i) * R + r0 + tx] = h; Tl[(size_t)(c0 + i) * R + r0 + tx] = l;
    }
}
__global__ void tbf16(const bf* __restrict__ ih, const bf* __restrict__ il, int R, int C,
                      bf* __restrict__ oh, bf* __restrict__ ol) {
    __shared__ bf th[32][33], tl[32][33];
    const int c0 = blockIdx.x * 32, r0 = blockIdx.y * 32, tx = threadIdx.x;
    for (int i = threadIdx.y; i < 32; i += 8) {
        th[i][tx] = ih[(size_t)(r0 + i) * C + c0 + tx];
        tl[i][tx] = il[(size_t)(r0 + i) * C + c0 + tx];
    }
    __syncthreads();
    for (int i = threadIdx.y; i < 32; i += 8) {
        oh[(size_t)(c0 + i) * R + r0 + tx] = th[tx][i];
        ol[(size_t)(c0 + i) * R + r0 + tx] = tl[tx][i];
    }
}
__global__ void colsum(const bf* __restrict__ h, const bf* __restrict__ l, int rows,
                       float* __restrict__ b, float lr) {
    int col = blockIdx.x * 32 + threadIdx.x;
    float s = 0.f;
    for (int r = threadIdx.y; r < rows; r += 8)
        s += __bfloat162float(h[(size_t)r * D_ + col]) + __bfloat162float(l[(size_t)r * D_ + col]);
    __shared__ float sm[8][33];
    sm[threadIdx.y][threadIdx.x] = s;
    __syncthreads();
    if (threadIdx.y == 0) {
        float t = 0.f;
#pragma unroll
        for (int y = 0; y < 8; y++) t += sm[y][threadIdx.x];
        b[col] -= lr * t;
    }
}

struct P_ {
    bf *xh, *xl, *Kh, *Kl, *Qh, *Ql, *Hqh, *Hql;
    float *V, *Pre, *W1, *W2, *b1, *b2;
    bf *H1h, *H1l, *dYh, *dYl, *dPh, *dPl;
    bf *H1th, *H1tl, *dYth, *dYtl, *dPth, *dPtl, *Kth, *Ktl;
    bf *W1Th, *W1Tl, *W2Th, *W2Tl, *W2h, *W2l, *WQTh, *WQTl, *WKVTh, *WKVTl;
};
static P_ getp() {
    static P_ p = [] {
        P_ s{};
        unsigned char* a;
        cudaGetSymbolAddress((void**)&a, g_arena);
        auto al = [&](size_t bytes) { unsigned char* r = a; a += (bytes + 1023) & ~1023ull; return r; };
        s.xh=(bf*)al(E1*2); s.xl=(bf*)al(E1*2); s.Kh=(bf*)al(E1*2); s.Kl=(bf*)al(E1*2);
        s.Qh=(bf*)al(E1*2); s.Ql=(bf*)al(E1*2); s.Hqh=(bf*)al(E1*2); s.Hql=(bf*)al(E1*2);
        s.V=(float*)al(E1*4); s.Pre=(float*)al(MCD*4);
        s.W1=(float*)al(DD*4); s.W2=(float*)al(DD*4); s.b1=(float*)al(D_*4); s.b2=(float*)al(D_*4);
        s.H1h=(bf*)al(MCD*2); s.H1l=(bf*)al(MCD*2); s.dYh=(bf*)al(MCD*2); s.dYl=(bf*)al(MCD*2);
        s.dPh=(bf*)al(MCD*2); s.dPl=(bf*)al(MCD*2);
        s.H1th=(bf*)al(MCD*2); s.H1tl=(bf*)al(MCD*2); s.dYth=(bf*)al(MCD*2); s.dYtl=(bf*)al(MCD*2);
        s.dPth=(bf*)al(MCD*2); s.dPtl=(bf*)al(MCD*2); s.Kth=(bf*)al(MCD*2); s.Ktl=(bf*)al(MCD*2);
        s.W1Th=(bf*)al(DD*2); s.W1Tl=(bf*)al(DD*2); s.W2Th=(bf*)al(DD*2); s.W2Tl=(bf*)al(DD*2);
        s.W2h=(bf*)al(DD*2); s.W2l=(bf*)al(DD*2); s.WQTh=(bf*)al(DD*2); s.WQTl=(bf*)al(DD*2);
        s.WKVTh=(bf*)al(DD*4); s.WKVTl=(bf*)al(DD*4);
        cudaFuncSetAttribute(gemm_tc<EPI_KV,false>,  cudaFuncAttributeMaxDynamicSharedMemorySize, SMEM_SZ);
        cudaFuncSetAttribute(gemm_tc<EPI_FWD,true>,  cudaFuncAttributeMaxDynamicSharedMemorySize, SMEM_SZ);
        cudaFuncSetAttribute(gemm_tc<EPI_DY,true>,   cudaFuncAttributeMaxDynamicSharedMemorySize, SMEM_SZ);
        cudaFuncSetAttribute(gemm_tc<EPI_DPRE,true>, cudaFuncAttributeMaxDynamicSharedMemorySize, SMEM_SZ);
        cudaFuncSetAttribute(gemm_tc<EPI_UPD,true>,  cudaFuncAttributeMaxDynamicSharedMemorySize, SMEM_SZ);
        cudaFuncSetAttribute(gemm_tc<EPI_SILU,false>,cudaFuncAttributeMaxDynamicSharedMemorySize, SMEM_SZ);
        cudaFuncSetAttribute(gemm_tc<EPI_OUT,false>, cudaFuncAttributeMaxDynamicSharedMemorySize, SMEM_SZ);
        cudaFuncSetAttribute(gemm_tc<EPI_Q,false>,   cudaFuncAttributeMaxDynamicSharedMemorySize, SMEM_SZ);
        return s;
    }();
    return p;
}

extern "C" void kernel_launch(void* const* d_in, const int* in_sizes, int n_in,
                              void* d_out, int out_size)
{
    const float* x   = (const float*)d_in[0];
    const float* WQ  = (const float*)d_in[1];
    const float* WKV = (const float*)d_in[2];
    const float* W1i = (const float*)d_in[3];
    const float* b1i = (const float*)d_in[4];
    const float* W2i = (const float*)d_in[5];
    const float* b2i = (const float*)d_in[6];
    float* out = (float*)d_out;
    P_ p = getp();
    const dim3 t8(32, 8);
    const float c2 = 2.f / (float)(B_ * D_);

    cudaMemcpyAsync(p.W1, W1i, DD * 4, cudaMemcpyDeviceToDevice);
    cudaMemcpyAsync(p.W2, W2i, DD * 4, cudaMemcpyDeviceToDevice);
    cudaMemcpyAsync(p.b1, b1i, D_ * 4, cudaMemcpyDeviceToDevice);
    cudaMemcpyAsync(p.b2, b2i, D_ * 4, cudaMemcpyDeviceToDevice);

    conv_x<<<E1 / 1024, 256>>>(x, p.xh, p.xl);
    tconv<<<dim3(32, 32), t8>>>(WQ, D_, D_, p.WQTh, p.WQTl, nullptr, nullptr);
    tconv<<<dim3(64, 32), t8>>>(WKV, D_, 2 * D_, p.WKVTh, p.WKVTl, nullptr, nullptr);
    tconv<<<dim3(32, 32), t8>>>(p.W1, D_, D_, p.W1Th, p.W1Tl, nullptr, nullptr);
    tconv<<<dim3(32, 32), t8>>>(p.W2, D_, D_, p.W2Th, p.W2Tl, p.W2h, p.W2l);

    gemm_tc<EPI_KV,false><<<dim3(16, 128), 256, SMEM_SZ>>>(
        p.xh, p.xl, p.WKVTh, p.WKVTl, D_, 2 * D_, 0, nullptr, nullptr,
        p.V, p.Kh, p.Kl, nullptr, nullptr, 0.f);

    for (int c = 0; c < NCH; c++) {
        const bf* Kch = p.Kh + (size_t)c * MCD;
        const bf* Kcl = p.Kl + (size_t)c * MCD;
        const float* Vc = p.V + (size_t)c * MCD;
        tbf16<<<dim3(32, 64), t8>>>(Kch, Kcl, MC, D_, p.Kth, p.Ktl);
        gemm_tc<EPI_FWD,true><<<dim3(8, 16), 256, SMEM_SZ>>>(
            Kch, Kcl, p.W1Th, p.W1Tl, D_, D_, MC, p.b1, nullptr,
            p.Pre, p.H1h, p.H1l, p.H1th, p.H1tl, 0.f);
        gemm_tc<EPI_DY,true><<<dim3(8, 16), 256, SMEM_SZ>>>(
            p.H1h, p.H1l, p.W2Th, p.W2Tl, D_, D_, MC, p.b2, Vc,
            nullptr, p.dYh, p.dYl, p.dYth, p.dYtl, c2);
        gemm_tc<EPI_DPRE,true><<<dim3(8, 16), 256, SMEM_SZ>>>(
            p.dYh, p.dYl, p.W2h, p.W2l, D_, D_, MC, nullptr, p.Pre,
            nullptr, p.dPh, p.dPl, p.dPth, p.dPtl, 0.f);
        gemm_tc<EPI_UPD,true><<<dim3(8, 8), 256, SMEM_SZ>>>(
            p.H1th, p.H1tl, p.dYth, p.dYtl, MC, D_, D_, nullptr, nullptr,
            p.W2, p.W2h, p.W2l, p.W2Th, p.W2Tl, LR_);
        colsum<<<32, t8>>>(p.dYh, p.dYl, MC, p.b2, LR_);
        gemm_tc<EPI_UPD,true><<<dim3(8, 8), 256, SMEM_SZ>>>(
            p.Kth, p.Ktl, p.dPth, p.dPtl, MC, D_, D_, nullptr, nullptr,
            p.W1, nullptr, nullptr, p.W1Th, p.W1Tl, LR_);
        colsum<<<32, t8>>>(p.dPh, p.dPl, MC, p.b1, LR_);
    }

    gemm_tc<EPI_Q,false><<<dim3(8, 128), 256, SMEM_SZ>>>(
        p.xh, p.xl, p.WQTh, p.WQTl, D_, D_, 0, nullptr, nullptr,
        nullptr, p.Qh, p.Ql, nullptr, nullptr, 0.f);
    gemm_tc<EPI_SILU,false><<<dim3(8, 128), 256, SMEM_SZ>>>(
        p.Qh, p.Ql, p.W1Th, p.W1Tl, D_, D_, 0, p.b1, nullptr,
        nullptr, p.Hqh, p.Hql, nullptr, nullptr, 0.f);
    gemm_tc<EPI_OUT,false><<<dim3(8, 128), 256, SMEM_SZ>>>(
        p.Hqh, p.Hql, p.W2Th, p.W2Tl, D_, D_, 0, p.b2, nullptr,
        out, nullptr, nullptr, nullptr, nullptr, 0.f);
}

// round 9
// speedup vs baseline: 6.0065x; 1.6763x over previous
#include <cuda_runtime.h>
#include <cuda_bf16.h>
#include <cstdint>

constexpr int S_ = 2048, B_ = 8, D_ = 1024;
constexpr int TCH = 256, NCH = S_ / TCH, MC = TCH * B_, SB = S_ * B_;
constexpr float LR_ = 1e-3f;
constexpr size_t E1 = (size_t)SB * D_;
constexpr size_t MCD = (size_t)MC * D_;
constexpr size_t DD = (size_t)D_ * D_;
constexpr size_t ARENA_BYTES = 460ull << 20;
static __device__ __align__(1024) unsigned char g_arena[ARENA_BYTES];
typedef __nv_bfloat16 bf;

constexpr int PITCH = 80;            // 32 bf16 + 16B pad
constexpr int TILE_B = 128 * PITCH;  // 10240
constexpr int SMEM_1T = 128 * 132 * 4;   // 67584 (epilogue stage dominates)
constexpr int SMEM_3T = 2 * 4 * TILE_B;  // 81920

__device__ __forceinline__ uint32_t s2u(const void* p) {
    uint32_t a;
    asm("{ .reg .u64 t; cvta.to.shared.u64 t, %1; cvt.u32.u64 %0, t; }" : "=r"(a) : "l"(p));
    return a;
}
__device__ __forceinline__ void cpa16(uint32_t dst, const void* src) {
    asm volatile("cp.async.cg.shared.global [%0], [%1], 16;" :: "r"(dst), "l"(src));
}
__device__ __forceinline__ void ldsm4(uint32_t* r, uint32_t a) {
    asm volatile("ldmatrix.sync.aligned.m8n8.x4.shared.b16 {%0,%1,%2,%3}, [%4];"
                 : "=r"(r[0]), "=r"(r[1]), "=r"(r[2]), "=r"(r[3]) : "r"(a));
}
__device__ __forceinline__ void mma16816(float* c, const uint32_t* a, const uint32_t* b) {
    asm volatile("mma.sync.aligned.m16n8k16.row.col.f32.bf16.bf16.f32 "
                 "{%0,%1,%2,%3}, {%4,%5,%6,%7}, {%8,%9}, {%0,%1,%2,%3};"
                 : "+f"(c[0]), "+f"(c[1]), "+f"(c[2]), "+f"(c[3])
                 : "r"(a[0]), "r"(a[1]), "r"(a[2]), "r"(a[3]), "r"(b[0]), "r"(b[1]));
}
__device__ __forceinline__ float sigf(float z) { return 1.f / (1.f + __expf(-z)); }
__device__ __forceinline__ void hilo(float v, bf& h, bf& l) {
    h = __float2bfloat16(v); l = __float2bfloat16(v - __bfloat162float(h));
}
enum { EPI_KV, EPI_FWD, EPI_DY, EPI_DPRE, EPI_UPD, EPI_SILU, EPI_OUT, EPI_Q };

// slot0=Ah, slot1=Bh, (SPLIT: slot2=Al, slot3=Bl)
template <bool SPLIT>
__device__ __forceinline__ void stage_load(
    uint32_t sbuf, const bf* Ah, const bf* Al, const bf* Bh, const bf* Bl,
    int m0, int n0, int K, int k0, int tid)
{
#pragma unroll
    for (int i = 0; i < 2; i++) {
        int idx = tid + i * 256, r = idx >> 2, c = idx & 3;
        cpa16(sbuf + r * PITCH + c * 16,          Ah + (size_t)(m0 + r) * K + k0 + c * 8);
        cpa16(sbuf + TILE_B + r * PITCH + c * 16, Bh + (size_t)(n0 + r) * K + k0 + c * 8);
        if (SPLIT) {
            cpa16(sbuf + 2 * TILE_B + r * PITCH + c * 16, Al + (size_t)(m0 + r) * K + k0 + c * 8);
            cpa16(sbuf + 3 * TILE_B + r * PITCH + c * 16, Bl + (size_t)(n0 + r) * K + k0 + c * 8);
        }
    }
    asm volatile("cp.async.commit_group;" ::: "memory");
}

// C[M,N] = A[M,K]*B[N,K]^T; SPLIT: 3-term split-bf16, else plain bf16
template <int EPI, bool OT, bool SPLIT>
__global__ __launch_bounds__(256, 2) void gemm_tc(
    const bf* __restrict__ Ah, const bf* __restrict__ Al,
    const bf* __restrict__ Bh, const bf* __restrict__ Bl,
    int K, int Nout, int mtot,
    const float* __restrict__ bias, const float* __restrict__ aux,
    float* __restrict__ f0, bf* __restrict__ oh, bf* __restrict__ ol,
    bf* __restrict__ oth, float scale)
{
    extern __shared__ __align__(128) char smem[];
    const uint32_t sbase = s2u(smem);
    const int tid = threadIdx.x, lane = tid & 31, wid = tid >> 5;
    const int warp_m = wid & 1, warp_n = wid >> 1;
    const int m0 = blockIdx.y * 128, n0 = blockIdx.x * 128;
    constexpr int SSTR = (SPLIT ? 4 : 2) * TILE_B;

    float acc[4][4][4];
#pragma unroll
    for (int a = 0; a < 4; a++)
#pragma unroll
        for (int b = 0; b < 4; b++)
#pragma unroll
            for (int e = 0; e < 4; e++) acc[a][b][e] = 0.f;

    const int nst = K >> 5;
    stage_load<SPLIT>(sbase, Ah, Al, Bh, Bl, m0, n0, K, 0, tid);

    for (int s = 0; s < nst; s++) {
        if (s + 1 < nst) {
            stage_load<SPLIT>(sbase + ((s + 1) & 1) * SSTR, Ah, Al, Bh, Bl,
                              m0, n0, K, (s + 1) * 32, tid);
            asm volatile("cp.async.wait_group 1;" ::: "memory");
        } else {
            asm volatile("cp.async.wait_group 0;" ::: "memory");
        }
        __syncthreads();
        const uint32_t st = sbase + (s & 1) * SSTR;
        const uint32_t sAh = st, sBh = st + TILE_B;
        const uint32_t sAl = st + 2 * TILE_B, sBl = st + 3 * TILE_B;

#pragma unroll
        for (int kc = 0; kc < 2; kc++) {
            uint32_t ra[4][4], rl[4][4];
            const uint32_t a_off = kc * 32 + (lane >> 4) * 16;
            const int arow = warp_m * 64 + (lane & 15);
#pragma unroll
            for (int mt = 0; mt < 4; mt++) {
                ldsm4(ra[mt], sAh + (arow + mt * 16) * PITCH + a_off);
                if (SPLIT) ldsm4(rl[mt], sAl + (arow + mt * 16) * PITCH + a_off);
            }
            const int browoff = ((lane >> 4) << 3) + (lane & 7);
            const uint32_t b_off = kc * 32 + (((lane >> 3) & 1) * 16);
#pragma unroll
            for (int np = 0; np < 2; np++) {
                uint32_t r4h[4], r4l[4];
                ldsm4(r4h, sBh + (warp_n * 32 + np * 16 + browoff) * PITCH + b_off);
                if (SPLIT) ldsm4(r4l, sBl + (warp_n * 32 + np * 16 + browoff) * PITCH + b_off);
#pragma unroll
                for (int hf = 0; hf < 2; hf++) {
                    const int nt = 2 * np + hf;
                    uint32_t bh2[2] = { r4h[2 * hf], r4h[2 * hf + 1] };
#pragma unroll
                    for (int mt = 0; mt < 4; mt++) {
                        mma16816(acc[mt][nt], ra[mt], bh2);
                        if (SPLIT) {
                            uint32_t bl2[2] = { r4l[2 * hf], r4l[2 * hf + 1] };
                            mma16816(acc[mt][nt], ra[mt], bl2);
                            mma16816(acc[mt][nt], rl[mt], bh2);
                        }
                    }
                }
            }
        }
        __syncthreads();
    }

    float* stg = reinterpret_cast<float*>(smem);
    {
        const int rb = warp_m * 64 + (lane >> 2);
        const int cb = warp_n * 32 + (lane & 3) * 2;
#pragma unroll
        for (int mt = 0; mt < 4; mt++)
#pragma unroll
            for (int nt = 0; nt < 4; nt++) {
                const int r = rb + mt * 16, c = cb + nt * 8;
                stg[r * 132 + c]           = acc[mt][nt][0];
                stg[r * 132 + c + 1]       = acc[mt][nt][1];
                stg[(r + 8) * 132 + c]     = acc[mt][nt][2];
                stg[(r + 8) * 132 + c + 1] = acc[mt][nt][3];
            }
    }
    __syncthreads();

    const int row = tid >> 1, col0 = (tid & 1) * 64;
    const int m = m0 + row;
#pragma unroll 2
    for (int j = 0; j < 64; j += 4) {
        float4 v4 = *reinterpret_cast<float4*>(&stg[row * 132 + col0 + j]);
        float vv[4] = { v4.x, v4.y, v4.z, v4.w };
        float fin[4];
        const int nb = n0 + col0 + j;
        if (EPI == EPI_KV) {
            const int bb = m >> 11, ss = m & (S_ - 1);
            const size_t base = (size_t)(ss * B_ + bb) * D_;
            if (nb < D_) {
                bf h[4];
#pragma unroll
                for (int e = 0; e < 4; e++) h[e] = __float2bfloat16(vv[e]);
                *reinterpret_cast<uint2*>(oh + base + nb) = *reinterpret_cast<uint2*>(h);
            } else {
                *reinterpret_cast<float4*>(f0 + base + nb - D_) = v4;
            }
            continue;
        }
#pragma unroll
        for (int e = 0; e < 4; e++) {
            const int n = nb + e;
            const float v = vv[e];
            if (EPI == EPI_FWD) {
                const float pre = v + bias[n];
                fin[e] = pre * sigf(pre);
            } else if (EPI == EPI_DY) {
                fin[e] = scale * (v + bias[n] - aux[(size_t)m * Nout + n]);
            } else if (EPI == EPI_DPRE) {
                const float z = aux[(size_t)m * Nout + n], sg = sigf(z);
                fin[e] = v * (sg * (1.f + z * (1.f - sg)));
            } else if (EPI == EPI_UPD) {
                fin[e] = f0[(size_t)m * Nout + n] - scale * v;
            } else if (EPI == EPI_SILU) {
                const float pre = v + bias[n];
                fin[e] = pre * sigf(pre);
            } else if (EPI == EPI_OUT) {
                fin[e] = v + bias[n];
            } else {  // EPI_Q
                fin[e] = v;
            }
        }
        if (EPI == EPI_FWD) {
            float4 pr; pr.x = vv[0] + bias[nb]; pr.y = vv[1] + bias[nb+1];
            pr.z = vv[2] + bias[nb+2]; pr.w = vv[3] + bias[nb+3];
            *reinterpret_cast<float4*>(f0 + (size_t)m * Nout + nb) = pr;
        }
        if (EPI == EPI_UPD || EPI == EPI_OUT) {
            float4 w; w.x = fin[0]; w.y = fin[1]; w.z = fin[2]; w.w = fin[3];
            if (f0) *reinterpret_cast<float4*>(f0 + (size_t)m * Nout + nb) = w;
        }
        if (oh) {
            if (SPLIT) {
                bf h[4], l[4];
#pragma unroll
                for (int e = 0; e < 4; e++) hilo(fin[e], h[e], l[e]);
                *reinterpret_cast<uint2*>(oh + (size_t)m * Nout + nb) = *reinterpret_cast<uint2*>(h);
                *reinterpret_cast<uint2*>(ol + (size_t)m * Nout + nb) = *reinterpret_cast<uint2*>(l);
            } else {
                bf h[4];
#pragma unroll
                for (int e = 0; e < 4; e++) h[e] = __float2bfloat16(fin[e]);
                *reinterpret_cast<uint2*>(oh + (size_t)m * Nout + nb) = *reinterpret_cast<uint2*>(h);
            }
        }
        if (OT) *reinterpret_cast<float4*>(&stg[row * 132 + col0 + j]) =
                    make_float4(fin[0], fin[1], fin[2], fin[3]);
    }

    if (OT) {  // transposed hi-only output (scan path)
        __syncthreads();
        const int nrow = tid >> 1, mc0 = (tid & 1) * 64;
        const size_t gn = (size_t)(n0 + nrow);
#pragma unroll 2
        for (int j0 = 0; j0 < 64; j0 += 8) {
            union { bf b[8]; uint4 u; } H;
#pragma unroll
            for (int j = 0; j < 8; j++)
                H.b[j] = __float2bfloat16(stg[(mc0 + j0 + j) * 132 + nrow]);
            *reinterpret_cast<uint4*>(oth + gn * mtot + (m0 + mc0 + j0)) = H.u;
        }
    }
}

__global__ __launch_bounds__(256) void conv_x(const float* __restrict__ in,
                                              bf* __restrict__ oh, bf* __restrict__ ol) {
    size_t i = (size_t)blockIdx.x * 1024 + threadIdx.x * 4;
    float4 v = *reinterpret_cast<const float4*>(in + i);
    bf h[4], l[4];
    hilo(v.x, h[0], l[0]); hilo(v.y, h[1], l[1]);
    hilo(v.z, h[2], l[2]); hilo(v.w, h[3], l[3]);
    *reinterpret_cast<uint2*>(oh + i) = *reinterpret_cast<uint2*>(h);
    *reinterpret_cast<uint2*>(ol + i) = *reinterpret_cast<uint2*>(l);
}
__global__ void tconv(const float* __restrict__ W, int R, int C,
                      bf* __restrict__ Th, bf* __restrict__ Tl,
                      bf* __restrict__ Nh) {
    __shared__ float t[32][33];
    const int c0 = blockIdx.x * 32, r0 = blockIdx.y * 32, tx = threadIdx.x;
    for (int i = threadIdx.y; i < 32; i += 8) {
        float v = W[(size_t)(r0 + i) * C + c0 + tx];
        t[i][tx] = v;
        if (Nh) Nh[(size_t)(r0 + i) * C + c0 + tx] = __float2bfloat16(v);
    }
    __syncthreads();
    for (int i = threadIdx.y; i < 32; i += 8) {
        bf h, l; hilo(t[tx][i], h, l);
        Th[(size_t)(c0 + i) * R + r0 + tx] = h;
        if (Tl) Tl[(size_t)(c0 + i) * R + r0 + tx] = l;
    }
}
__global__ void tbf16h(const bf* __restrict__ ih, int R, int C, bf* __restrict__ oh) {
    __shared__ bf th[32][33];
    const int c0 = blockIdx.x * 32, r0 = blockIdx.y * 32, tx = threadIdx.x;
    for (int i = threadIdx.y; i < 32; i += 8)
        th[i][tx] = ih[(size_t)(r0 + i) * C + c0 + tx];
    __syncthreads();
    for (int i = threadIdx.y; i < 32; i += 8)
        oh[(size_t)(c0 + i) * R + r0 + tx] = th[tx][i];
}
__global__ void colsum(const bf* __restrict__ h, int rows, float* __restrict__ b, float lr) {
    int col = blockIdx.x * 32 + threadIdx.x;
    float s = 0.f;
    for (int r = threadIdx.y; r < rows; r += 8)
        s += __bfloat162float(h[(size_t)r * D_ + col]);
    __shared__ float sm[8][33];
    sm[threadIdx.y][threadIdx.x] = s;
    __syncthreads();
    if (threadIdx.y == 0) {
        float t = 0.f;
#pragma unroll
        for (int y = 0; y < 8; y++) t += sm[y][threadIdx.x];
        b[col] -= lr * t;
    }
}

struct P_ {
    bf *xh, *xl, *Kh, *Qh, *Ql, *Hqh, *Hql;
    float *V, *Pre, *W1, *W2, *b1, *b2;
    bf *H1h, *dYh, *dPh, *H1th, *dYth, *dPth, *Kth;
    bf *W1Th, *W1Tl, *W2Th, *W2Tl, *W2h, *WQTh, *WQTl, *WKVTh;
};
static P_ getp() {
    static P_ p = [] {
        P_ s{};
        unsigned char* a;
        cudaGetSymbolAddress((void**)&a, g_arena);
        auto al = [&](size_t bytes) { unsigned char* r = a; a += (bytes + 1023) & ~1023ull; return r; };
        s.xh=(bf*)al(E1*2); s.xl=(bf*)al(E1*2); s.Kh=(bf*)al(E1*2);
        s.Qh=(bf*)al(E1*2); s.Ql=(bf*)al(E1*2); s.Hqh=(bf*)al(E1*2); s.Hql=(bf*)al(E1*2);
        s.V=(float*)al(E1*4); s.Pre=(float*)al(MCD*4);
        s.W1=(float*)al(DD*4); s.W2=(float*)al(DD*4); s.b1=(float*)al(D_*4); s.b2=(float*)al(D_*4);
        s.H1h=(bf*)al(MCD*2); s.dYh=(bf*)al(MCD*2); s.dPh=(bf*)al(MCD*2);
        s.H1th=(bf*)al(MCD*2); s.dYth=(bf*)al(MCD*2); s.dPth=(bf*)al(MCD*2); s.Kth=(bf*)al(MCD*2);
        s.W1Th=(bf*)al(DD*2); s.W1Tl=(bf*)al(DD*2); s.W2Th=(bf*)al(DD*2); s.W2Tl=(bf*)al(DD*2);
        s.W2h=(bf*)al(DD*2); s.WQTh=(bf*)al(DD*2); s.WQTl=(bf*)al(DD*2);
        s.WKVTh=(bf*)al(DD*4);
        cudaFuncSetAttribute(gemm_tc<EPI_KV,false,false>,  cudaFuncAttributeMaxDynamicSharedMemorySize, SMEM_1T);
        cudaFuncSetAttribute(gemm_tc<EPI_FWD,true,false>,  cudaFuncAttributeMaxDynamicSharedMemorySize, SMEM_1T);
        cudaFuncSetAttribute(gemm_tc<EPI_DY,true,false>,   cudaFuncAttributeMaxDynamicSharedMemorySize, SMEM_1T);
        cudaFuncSetAttribute(gemm_tc<EPI_DPRE,true,false>, cudaFuncAttributeMaxDynamicSharedMemorySize, SMEM_1T);
        cudaFuncSetAttribute(gemm_tc<EPI_UPD,true,false>,  cudaFuncAttributeMaxDynamicSharedMemorySize, SMEM_1T);
        cudaFuncSetAttribute(gemm_tc<EPI_Q,false,true>,    cudaFuncAttributeMaxDynamicSharedMemorySize, SMEM_3T);
        cudaFuncSetAttribute(gemm_tc<EPI_SILU,false,true>, cudaFuncAttributeMaxDynamicSharedMemorySize, SMEM_3T);
        cudaFuncSetAttribute(gemm_tc<EPI_OUT,false,true>,  cudaFuncAttributeMaxDynamicSharedMemorySize, SMEM_3T);
        return s;
    }();
    return p;
}

extern "C" void kernel_launch(void* const* d_in, const int* in_sizes, int n_in,
                              void* d_out, int out_size)
{
    const float* x   = (const float*)d_in[0];
    const float* WQ  = (const float*)d_in[1];
    const float* WKV = (const float*)d_in[2];
    const float* W1i = (const float*)d_in[3];
    const float* b1i = (const float*)d_in[4];
    const float* W2i = (const float*)d_in[5];
    const float* b2i = (const float*)d_in[6];
    float* out = (float*)d_out;
    P_ p = getp();
    const dim3 t8(32, 8);
    const float c2 = 2.f / (float)(B_ * D_);

    cudaMemcpyAsync(p.W1, W1i, DD * 4, cudaMemcpyDeviceToDevice);
    cudaMemcpyAsync(p.W2, W2i, DD * 4, cudaMemcpyDeviceToDevice);
    cudaMemcpyAsync(p.b1, b1i, D_ * 4, cudaMemcpyDeviceToDevice);
    cudaMemcpyAsync(p.b2, b2i, D_ * 4, cudaMemcpyDeviceToDevice);

    conv_x<<<E1 / 1024, 256>>>(x, p.xh, p.xl);
    tconv<<<dim3(32, 32), t8>>>(WQ, D_, D_, p.WQTh, p.WQTl, nullptr);
    tconv<<<dim3(64, 32), t8>>>(WKV, D_, 2 * D_, p.WKVTh, nullptr, nullptr);
    tconv<<<dim3(32, 32), t8>>>(p.W1, D_, D_, p.W1Th, nullptr, nullptr);
    tconv<<<dim3(32, 32), t8>>>(p.W2, D_, D_, p.W2Th, nullptr, p.W2h);

    // kv = x @ W_KV (1-term) -> Kh bf16 + V fp32, step-major
    gemm_tc<EPI_KV,false,false><<<dim3(16, 128), 256, SMEM_1T>>>(
        p.xh, nullptr, p.WKVTh, nullptr, D_, 2 * D_, 0, nullptr, nullptr,
        p.V, p.Kh, nullptr, nullptr, 0.f);

    for (int c = 0; c < NCH; c++) {
        const bf* Kch = p.Kh + (size_t)c * MCD;
        const float* Vc = p.V + (size_t)c * MCD;
        tbf16h<<<dim3(32, 64), t8>>>(Kch, MC, D_, p.Kth);
        gemm_tc<EPI_FWD,true,false><<<dim3(8, 16), 256, SMEM_1T>>>(
            Kch, nullptr, p.W1Th, nullptr, D_, D_, MC, p.b1, nullptr,
            p.Pre, p.H1h, nullptr, p.H1th, 0.f);
        gemm_tc<EPI_DY,true,false><<<dim3(8, 16), 256, SMEM_1T>>>(
            p.H1h, nullptr, p.W2Th, nullptr, D_, D_, MC, p.b2, Vc,
            nullptr, p.dYh, nullptr, p.dYth, c2);
        gemm_tc<EPI_DPRE,true,false><<<dim3(8, 16), 256, SMEM_1T>>>(
            p.dYh, nullptr, p.W2h, nullptr, D_, D_, MC, nullptr, p.Pre,
            nullptr, p.dPh, nullptr, p.dPth, 0.f);
        gemm_tc<EPI_UPD,true,false><<<dim3(8, 8), 256, SMEM_1T>>>(
            p.H1th, nullptr, p.dYth, nullptr, MC, D_, D_, nullptr, nullptr,
            p.W2, p.W2h, nullptr, p.W2Th, LR_);
        colsum<<<32, t8>>>(p.dYh, MC, p.b2, LR_);
        gemm_tc<EPI_UPD,true,false><<<dim3(8, 8), 256, SMEM_1T>>>(
            p.Kth, nullptr, p.dPth, nullptr, MC, D_, D_, nullptr, nullptr,
            p.W1, nullptr, nullptr, p.W1Th, LR_);
        colsum<<<32, t8>>>(p.dPh, MC, p.b1, LR_);
    }

    // final split weights for the 3-term retrieval path
    tconv<<<dim3(32, 32), t8>>>(p.W1, D_, D_, p.W1Th, p.W1Tl, nullptr);
    tconv<<<dim3(32, 32), t8>>>(p.W2, D_, D_, p.W2Th, p.W2Tl, nullptr);

    gemm_tc<EPI_Q,false,true><<<dim3(8, 128), 256, SMEM_3T>>>(
        p.xh, p.xl, p.WQTh, p.WQTl, D_, D_, 0, nullptr, nullptr,
        nullptr, p.Qh, p.Ql, nullptr, 0.f);
    gemm_tc<EPI_SILU,false,true><<<dim3(8, 128), 256, SMEM_3T>>>(
        p.Qh, p.Ql, p.W1Th, p.W1Tl, D_, D_, 0, p.b1, nullptr,
        nullptr, p.Hqh, p.Hql, nullptr, 0.f);
    gemm_tc<EPI_OUT,false,true><<<dim3(8, 128), 256, SMEM_3T>>>(
        p.Hqh, p.Hql, p.W2Th, p.W2Tl, D_, D_, 0, p.b2, nullptr,
        out, nullptr, nullptr, nullptr, 0.f);
}

// round 11
// speedup vs baseline: 7.1014x; 1.1823x over previous
#include <cuda_runtime.h>
#include <cuda_bf16.h>
#include <cstdint>

constexpr int S_ = 2048, B_ = 8, D_ = 1024;
constexpr int TCH = 256, NCH = S_ / TCH, MC = TCH * B_, SB = S_ * B_;
constexpr float LR_ = 1e-3f;
constexpr size_t E1 = (size_t)SB * D_;
constexpr size_t MCD = (size_t)MC * D_;
constexpr size_t DD = (size_t)D_ * D_;
constexpr size_t ARENA_BYTES = 460ull << 20;
static __device__ __align__(1024) unsigned char g_arena[ARENA_BYTES];
typedef __nv_bfloat16 bf;

constexpr int TILE_B = 128 * 80;          // A tile bytes (128 rows x 80B pitch)
constexpr int SMEM_1T4 = 128 * 132 * 4;   // 67584  (NWN4 1-term: epilogue stage dominates)
constexpr int SMEM_3T4 = 2 * 4 * TILE_B;  // 81920  (NWN4 3-term mainloop dominates)
constexpr int SMEM_2  = 128 * 68 * 4;     // 34816  (NWN2: epilogue stage dominates)

__device__ __forceinline__ uint32_t s2u(const void* p) {
    uint32_t a;
    asm("{ .reg .u64 t; cvta.to.shared.u64 t, %1; cvt.u32.u64 %0, t; }" : "=r"(a) : "l"(p));
    return a;
}
__device__ __forceinline__ void cpa16(uint32_t dst, const void* src) {
    asm volatile("cp.async.cg.shared.global [%0], [%1], 16;" :: "r"(dst), "l"(src));
}
__device__ __forceinline__ void ldsm4(uint32_t* r, uint32_t a) {
    asm volatile("ldmatrix.sync.aligned.m8n8.x4.shared.b16 {%0,%1,%2,%3}, [%4];"
                 : "=r"(r[0]), "=r"(r[1]), "=r"(r[2]), "=r"(r[3]) : "r"(a));
}
__device__ __forceinline__ void mma16816(float* c, const uint32_t* a, const uint32_t* b) {
    asm volatile("mma.sync.aligned.m16n8k16.row.col.f32.bf16.bf16.f32 "
                 "{%0,%1,%2,%3}, {%4,%5,%6,%7}, {%8,%9}, {%0,%1,%2,%3};"
                 : "+f"(c[0]), "+f"(c[1]), "+f"(c[2]), "+f"(c[3])
                 : "r"(a[0]), "r"(a[1]), "r"(a[2]), "r"(a[3]), "r"(b[0]), "r"(b[1]));
}
__device__ __forceinline__ float sigf(float z) { return 1.f / (1.f + __expf(-z)); }
__device__ __forceinline__ void hilo(float v, bf& h, bf& l) {
    h = __float2bfloat16(v); l = __float2bfloat16(v - __bfloat162float(h));
}
enum { EPI_KV, EPI_FWD, EPI_DY, EPI_DPRE, EPI_UPD, EPI_SILU, EPI_OUT, EPI_Q };

template <bool SPLIT, int NWN>
__device__ __forceinline__ void stage_load(
    uint32_t sbuf, const bf* Ah, const bf* Al, const bf* Bh, const bf* Bl,
    int m0, int n0, int K, int k0, int tid)
{
    constexpr int BN = 32 * NWN, NT = 64 * NWN, BNB = BN * 80;
    constexpr int CA = 512, CB = BN * 4;
    constexpr int TOT = (SPLIT ? 2 : 1) * (CA + CB);
#pragma unroll
    for (int idx = tid; idx < TOT; idx += NT) {
        int t = idx, off, row0; const bf* g;
        if (t < CA)                { g = Ah; row0 = m0; off = 0; }
        else if (t < CA + CB)      { t -= CA; g = Bh; row0 = n0; off = TILE_B; }
        else if (t < 2 * CA + CB)  { t -= CA + CB; g = Al; row0 = m0; off = TILE_B + BNB; }
        else                       { t -= 2 * CA + CB; g = Bl; row0 = n0; off = 2 * TILE_B + BNB; }
        int r = t >> 2, c = t & 3;
        cpa16(sbuf + off + r * 80 + c * 16, g + (size_t)(row0 + r) * K + k0 + c * 8);
    }
    asm volatile("cp.async.commit_group;" ::: "memory");
}

// C[M,N] = A[M,K]*B[N,K]^T.  NWN=4: 128x128 tile/256thr; NWN=2: 128x64/128thr.
// DUAL: blockIdx.z==1 uses (Al,Bl) as A/B and (f0b,othb) outputs (oh disabled).
template <int EPI, bool OT, bool SPLIT, int NWN, bool DUAL>
__global__ __launch_bounds__(64 * NWN, NWN == 4 ? 2 : 3) void gemm_tc(
    const bf* __restrict__ Ah, const bf* __restrict__ Al,
    const bf* __restrict__ Bh, const bf* __restrict__ Bl,
    int K, int Nout, int mtot,
    const float* __restrict__ bias, const float* __restrict__ aux,
    float* f0, bf* oh, bf* __restrict__ ol,
    bf* oth, float* f0b, bf* othb, float scale)
{
    constexpr int BN = 32 * NWN, BNB = BN * 80, PCH = BN + 4, CPR = NWN / 2;
    constexpr int SSTR = (SPLIT ? 2 : 1) * (TILE_B + BNB);
    extern __shared__ __align__(128) char smem[];
    const uint32_t sbase = s2u(smem);
    const int tid = threadIdx.x, lane = tid & 31, wid = tid >> 5;
    const int warp_m = wid & 1, warp_n = wid >> 1;
    const int m0 = blockIdx.y * 128, n0 = blockIdx.x * BN;

    const bf *A = Ah, *Bm = Bh;
    if (DUAL && blockIdx.z == 1) { A = Al; Bm = Bl; f0 = f0b; oh = nullptr; oth = othb; }

    float acc[4][4][4];
#pragma unroll
    for (int a = 0; a < 4; a++)
#pragma unroll
        for (int b = 0; b < 4; b++)
#pragma unroll
            for (int e = 0; e < 4; e++) acc[a][b][e] = 0.f;

    const int nst = K >> 5;
    stage_load<SPLIT, NWN>(sbase, A, Al, Bm, Bl, m0, n0, K, 0, tid);

    for (int s = 0; s < nst; s++) {
        if (s + 1 < nst) {
            stage_load<SPLIT, NWN>(sbase + ((s + 1) & 1) * SSTR, A, Al, Bm, Bl,
                                   m0, n0, K, (s + 1) * 32, tid);
            asm volatile("cp.async.wait_group 1;" ::: "memory");
        } else {
            asm volatile("cp.async.wait_group 0;" ::: "memory");
        }
        __syncthreads();
        const uint32_t st = sbase + (s & 1) * SSTR;
        const uint32_t sAh = st, sBh = st + TILE_B;
        const uint32_t sAl = st + TILE_B + BNB, sBl = sAl + TILE_B;

#pragma unroll
        for (int kc = 0; kc < 2; kc++) {
            uint32_t ra[4][4], rl[4][4];
            const uint32_t a_off = kc * 32 + (lane >> 4) * 16;
            const int arow = warp_m * 64 + (lane & 15);
#pragma unroll
            for (int mt = 0; mt < 4; mt++) {
                ldsm4(ra[mt], sAh + (arow + mt * 16) * 80 + a_off);
                if (SPLIT) ldsm4(rl[mt], sAl + (arow + mt * 16) * 80 + a_off);
            }
            const int browoff = ((lane >> 4) << 3) + (lane & 7);
            const uint32_t b_off = kc * 32 + (((lane >> 3) & 1) * 16);
#pragma unroll
            for (int np = 0; np < 2; np++) {
                uint32_t r4h[4], r4l[4];
                ldsm4(r4h, sBh + (warp_n * 32 + np * 16 + browoff) * 80 + b_off);
                if (SPLIT) ldsm4(r4l, sBl + (warp_n * 32 + np * 16 + browoff) * 80 + b_off);
#pragma unroll
                for (int hf = 0; hf < 2; hf++) {
                    const int nt = 2 * np + hf;
                    uint32_t bh2[2] = { r4h[2 * hf], r4h[2 * hf + 1] };
#pragma unroll
                    for (int mt = 0; mt < 4; mt++) {
                        mma16816(acc[mt][nt], ra[mt], bh2);
                        if (SPLIT) {
                            uint32_t bl2[2] = { r4l[2 * hf], r4l[2 * hf + 1] };
                            mma16816(acc[mt][nt], ra[mt], bl2);
                            mma16816(acc[mt][nt], rl[mt], bh2);
                        }
                    }
                }
            }
        }
        __syncthreads();
    }

    float* stg = reinterpret_cast<float*>(smem);
    {
        const int rb = warp_m * 64 + (lane >> 2);
        const int cb = warp_n * 32 + (lane & 3) * 2;
#pragma unroll
        for (int mt = 0; mt < 4; mt++)
#pragma unroll
            for (int nt = 0; nt < 4; nt++) {
                const int r = rb + mt * 16, c = cb + nt * 8;
                stg[r * PCH + c]           = acc[mt][nt][0];
                stg[r * PCH + c + 1]       = acc[mt][nt][1];
                stg[(r + 8) * PCH + c]     = acc[mt][nt][2];
                stg[(r + 8) * PCH + c + 1] = acc[mt][nt][3];
            }
    }
    __syncthreads();

    const int row = tid / CPR, col0 = (tid % CPR) * 64;
    const int m = m0 + row;
#pragma unroll 2
    for (int j = 0; j < 64; j += 4) {
        float4 v4 = *reinterpret_cast<float4*>(&stg[row * PCH + col0 + j]);
        float vv[4] = { v4.x, v4.y, v4.z, v4.w };
        float fin[4];
        const int nb = n0 + col0 + j;
        if (EPI == EPI_KV) {
            const int bb = m >> 11, ss = m & (S_ - 1);
            const size_t base = (size_t)(ss * B_ + bb) * D_;
            if (nb < D_) {
                bf h[4];
#pragma unroll
                for (int e = 0; e < 4; e++) h[e] = __float2bfloat16(vv[e]);
                *reinterpret_cast<uint2*>(oh + base + nb) = *reinterpret_cast<uint2*>(h);
            } else {
                *reinterpret_cast<float4*>(f0 + base + nb - D_) = v4;
            }
            continue;
        }
#pragma unroll
        for (int e = 0; e < 4; e++) {
            const int n = nb + e;
            const float v = vv[e];
            if (EPI == EPI_FWD) {
                const float pre = v + bias[n];
                fin[e] = pre * sigf(pre);
            } else if (EPI == EPI_DY) {
                fin[e] = scale * (v + bias[n] - aux[(size_t)m * Nout + n]);
            } else if (EPI == EPI_DPRE) {
                const float z = aux[(size_t)m * Nout + n], sg = sigf(z);
                fin[e] = v * (sg * (1.f + z * (1.f - sg)));
            } else if (EPI == EPI_UPD) {
                fin[e] = f0[(size_t)m * Nout + n] - scale * v;
            } else if (EPI == EPI_SILU) {
                const float pre = v + bias[n];
                fin[e] = pre * sigf(pre);
            } else if (EPI == EPI_OUT) {
                fin[e] = v + bias[n];
            } else {  // EPI_Q
                fin[e] = v;
            }
        }
        if (EPI == EPI_FWD) {
            float4 pr; pr.x = vv[0] + bias[nb]; pr.y = vv[1] + bias[nb+1];
            pr.z = vv[2] + bias[nb+2]; pr.w = vv[3] + bias[nb+3];
            *reinterpret_cast<float4*>(f0 + (size_t)m * Nout + nb) = pr;
        }
        if (EPI == EPI_UPD || EPI == EPI_OUT) {
            float4 w; w.x = fin[0]; w.y = fin[1]; w.z = fin[2]; w.w = fin[3];
            if (f0) *reinterpret_cast<float4*>(f0 + (size_t)m * Nout + nb) = w;
        }
        if (oh) {
            if (SPLIT) {
                bf h[4], l[4];
#pragma unroll
                for (int e = 0; e < 4; e++) hilo(fin[e], h[e], l[e]);
                *reinterpret_cast<uint2*>(oh + (size_t)m * Nout + nb) = *reinterpret_cast<uint2*>(h);
                *reinterpret_cast<uint2*>(ol + (size_t)m * Nout + nb) = *reinterpret_cast<uint2*>(l);
            } else {
                bf h[4];
#pragma unroll
                for (int e = 0; e < 4; e++) h[e] = __float2bfloat16(fin[e]);
                *reinterpret_cast<uint2*>(oh + (size_t)m * Nout + nb) = *reinterpret_cast<uint2*>(h);
            }
        }
        if (OT) *reinterpret_cast<float4*>(&stg[row * PCH + col0 + j]) =
                    make_float4(fin[0], fin[1], fin[2], fin[3]);
    }

    if (OT) {
        __syncthreads();
        const int nrow = tid >> 1, mc0 = (tid & 1) * 64;
        const size_t gn = (size_t)(n0 + nrow);
#pragma unroll 2
        for (int j0 = 0; j0 < 64; j0 += 8) {
            union { bf b[8]; uint4 u; } H;
#pragma unroll
            for (int j = 0; j < 8; j++)
                H.b[j] = __float2bfloat16(stg[(mc0 + j0 + j) * PCH + nrow]);
            *reinterpret_cast<uint4*>(oth + gn * mtot + (m0 + mc0 + j0)) = H.u;
        }
    }
}

__global__ __launch_bounds__(256) void conv_x(const float* __restrict__ in,
                                              bf* __restrict__ oh, bf* __restrict__ ol) {
    size_t i = (size_t)blockIdx.x * 1024 + threadIdx.x * 4;
    float4 v = *reinterpret_cast<const float4*>(in + i);
    bf h[4], l[4];
    hilo(v.x, h[0], l[0]); hilo(v.y, h[1], l[1]);
    hilo(v.z, h[2], l[2]); hilo(v.w, h[3], l[3]);
    *reinterpret_cast<uint2*>(oh + i) = *reinterpret_cast<uint2*>(h);
    *reinterpret_cast<uint2*>(ol + i) = *reinterpret_cast<uint2*>(l);
}
__global__ void tconv(const float* __restrict__ W, int R, int C,
                      bf* __restrict__ Th, bf* __restrict__ Tl, bf* __restrict__ Nh) {
    __shared__ float t[32][33];
    const int c0 = blockIdx.x * 32, r0 = blockIdx.y * 32, tx = threadIdx.x;
    for (int i = threadIdx.y; i < 32; i += 8) {
        float v = W[(size_t)(r0 + i) * C + c0 + tx];
        t[i][tx] = v;
        if (Nh) Nh[(size_t)(r0 + i) * C + c0 + tx] = __float2bfloat16(v);
    }
    __syncthreads();
    for (int i = threadIdx.y; i < 32; i += 8) {
        bf h, l; hilo(t[tx][i], h, l);
        Th[(size_t)(c0 + i) * R + r0 + tx] = h;
        if (Tl) Tl[(size_t)(c0 + i) * R + r0 + tx] = l;
    }
}
// batched chunk transpose: z = chunk index
__global__ void tbf16b(const bf* __restrict__ ih, int R, int C, bf* __restrict__ oh) {
    ih += (size_t)blockIdx.z * MCD;
    oh += (size_t)blockIdx.z * MCD;
    __shared__ bf th[32][33];
    const int c0 = blockIdx.x * 32, r0 = blockIdx.y * 32, tx = threadIdx.x;
    for (int i = threadIdx.y; i < 32; i += 8)
        th[i][tx] = ih[(size_t)(r0 + i) * C + c0 + tx];
    __syncthreads();
    for (int i = threadIdx.y; i < 32; i += 8)
        oh[(size_t)(c0 + i) * R + r0 + tx] = th[tx][i];
}
// fused bias updates: y=0: b2 -= lr*colsum(dY); y=1: b1 -= lr*colsum(dP)
__global__ void colsum2(const bf* __restrict__ dY, const bf* __restrict__ dP,
                        int rows, float* __restrict__ b2, float* __restrict__ b1, float lr) {
    const bf* src = blockIdx.y ? dP : dY;
    float* b = blockIdx.y ? b1 : b2;
    int col = blockIdx.x * 32 + threadIdx.x;
    float s = 0.f;
    for (int r = threadIdx.y; r < rows; r += 8)
        s += __bfloat162float(src[(size_t)r * D_ + col]);
    __shared__ float sm[8][33];
    sm[threadIdx.y][threadIdx.x] = s;
    __syncthreads();
    if (threadIdx.y == 0) {
        float t = 0.f;
#pragma unroll
        for (int y = 0; y < 8; y++) t += sm[y][threadIdx.x];
        b[col] -= lr * t;
    }
}

struct P_ {
    bf *xh, *xl, *Kh, *Qh, *Ql, *Hqh, *Hql;
    float *V, *Pre, *W1, *W2, *b1, *b2;
    bf *H1h, *dYh, *dPh, *H1th, *dYth, *dPth, *Kta;
    bf *W1Th, *W1Tl, *W2Th, *W2Tl, *W2h, *WQTh, *WQTl, *WKVTh;
};
static P_ getp() {
    static P_ p = [] {
        P_ s{};
        unsigned char* a;
        cudaGetSymbolAddress((void**)&a, g_arena);
        auto al = [&](size_t bytes) { unsigned char* r = a; a += (bytes + 1023) & ~1023ull; return r; };
        s.xh=(bf*)al(E1*2); s.xl=(bf*)al(E1*2); s.Kh=(bf*)al(E1*2);
        s.Qh=(bf*)al(E1*2); s.Ql=(bf*)al(E1*2); s.Hqh=(bf*)al(E1*2); s.Hql=(bf*)al(E1*2);
        s.V=(float*)al(E1*4); s.Pre=(float*)al(MCD*4);
        s.W1=(float*)al(DD*4); s.W2=(float*)al(DD*4); s.b1=(float*)al(D_*4); s.b2=(float*)al(D_*4);
        s.H1h=(bf*)al(MCD*2); s.dYh=(bf*)al(MCD*2); s.dPh=(bf*)al(MCD*2);
        s.H1th=(bf*)al(MCD*2); s.dYth=(bf*)al(MCD*2); s.dPth=(bf*)al(MCD*2);
        s.Kta=(bf*)al(NCH*MCD*2);
        s.W1Th=(bf*)al(DD*2); s.W1Tl=(bf*)al(DD*2); s.W2Th=(bf*)al(DD*2); s.W2Tl=(bf*)al(DD*2);
        s.W2h=(bf*)al(DD*2); s.WQTh=(bf*)al(DD*2); s.WQTl=(bf*)al(DD*2);
        s.WKVTh=(bf*)al(DD*4);
        cudaFuncSetAttribute(gemm_tc<EPI_KV,false,false,4,false>,  cudaFuncAttributeMaxDynamicSharedMemorySize, SMEM_1T4);
        cudaFuncSetAttribute(gemm_tc<EPI_FWD,true,false,2,false>,  cudaFuncAttributeMaxDynamicSharedMemorySize, SMEM_2);
        cudaFuncSetAttribute(gemm_tc<EPI_DY,true,false,2,false>,   cudaFuncAttributeMaxDynamicSharedMemorySize, SMEM_2);
        cudaFuncSetAttribute(gemm_tc<EPI_DPRE,true,false,2,false>, cudaFuncAttributeMaxDynamicSharedMemorySize, SMEM_2);
        cudaFuncSetAttribute(gemm_tc<EPI_UPD,true,false,2,true>,   cudaFuncAttributeMaxDynamicSharedMemorySize, SMEM_2);
        cudaFuncSetAttribute(gemm_tc<EPI_Q,false,true,4,false>,    cudaFuncAttributeMaxDynamicSharedMemorySize, SMEM_3T4);
        cudaFuncSetAttribute(gemm_tc<EPI_SILU,false,true,4,false>, cudaFuncAttributeMaxDynamicSharedMemorySize, SMEM_3T4);
        cudaFuncSetAttribute(gemm_tc<EPI_OUT,false,true,4,false>,  cudaFuncAttributeMaxDynamicSharedMemorySize, SMEM_3T4);
        return s;
    }();
    return p;
}

extern "C" void kernel_launch(void* const* d_in, const int* in_sizes, int n_in,
                              void* d_out, int out_size)
{
    const float* x   = (const float*)d_in[0];
    const float* WQ  = (const float*)d_in[1];
    const float* WKV = (const float*)d_in[2];
    const float* W1i = (const float*)d_in[3];
    const float* b1i = (const float*)d_in[4];
    const float* W2i = (const float*)d_in[5];
    const float* b2i = (const float*)d_in[6];
    float* out = (float*)d_out;
    P_ p = getp();
    const dim3 t8(32, 8);
    const float c2 = 2.f / (float)(B_ * D_);

    cudaMemcpyAsync(p.W1, W1i, DD * 4, cudaMemcpyDeviceToDevice);
    cudaMemcpyAsync(p.W2, W2i, DD * 4, cudaMemcpyDeviceToDevice);
    cudaMemcpyAsync(p.b1, b1i, D_ * 4, cudaMemcpyDeviceToDevice);
    cudaMemcpyAsync(p.b2, b2i, D_ * 4, cudaMemcpyDeviceToDevice);

    conv_x<<<E1 / 1024, 256>>>(x, p.xh, p.xl);
    tconv<<<dim3(32, 32), t8>>>(WQ, D_, D_, p.WQTh, p.WQTl, nullptr);
    tconv<<<dim3(64, 32), t8>>>(WKV, D_, 2 * D_, p.WKVTh, nullptr, nullptr);
    tconv<<<dim3(32, 32), t8>>>(p.W1, D_, D_, p.W1Th, nullptr, nullptr);
    tconv<<<dim3(32, 32), t8>>>(p.W2, D_, D_, p.W2Th, nullptr, p.W2h);

    // kv = x @ W_KV (1-term) -> Kh bf16 + V fp32, step-major
    gemm_tc<EPI_KV,false,false,4,false><<<dim3(16, 128), 256, SMEM_1T4>>>(
        p.xh, nullptr, p.WKVTh, nullptr, D_, 2 * D_, 0, nullptr, nullptr,
        p.V, p.Kh, nullptr, nullptr, nullptr, nullptr, 0.f);

    // all chunk K transposes in one launch
    tbf16b<<<dim3(32, 64, NCH), t8>>>(p.Kh, MC, D_, p.Kta);

    for (int c = 0; c < NCH; c++) {
        const bf* Kch = p.Kh + (size_t)c * MCD;
        const bf* Kth = p.Kta + (size_t)c * MCD;
        const float* Vc = p.V + (size_t)c * MCD;
        gemm_tc<EPI_FWD,true,false,2,false><<<dim3(16, 16), 128, SMEM_2>>>(
            Kch, nullptr, p.W1Th, nullptr, D_, D_, MC, p.b1, nullptr,
            p.Pre, p.H1h, nullptr, p.H1th, nullptr, nullptr, 0.f);
        gemm_tc<EPI_DY,true,false,2,false><<<dim3(16, 16), 128, SMEM_2>>>(
            p.H1h, nullptr, p.W2Th, nullptr, D_, D_, MC, p.b2, Vc,
            nullptr, p.dYh, nullptr, p.dYth, nullptr, nullptr, c2);
        gemm_tc<EPI_DPRE,true,false,2,false><<<dim3(16, 16), 128, SMEM_2>>>(
            p.dYh, nullptr, p.W2h, nullptr, D_, D_, MC, nullptr, p.Pre,
            nullptr, p.dPh, nullptr, p.dPth, nullptr, nullptr, 0.f);
        // fused: z=0 W2 -= lr*H1t@dYt ; z=1 W1 -= lr*Kt@dPt
        gemm_tc<EPI_UPD,true,false,2,true><<<dim3(16, 8, 2), 128, SMEM_2>>>(
            p.H1th, Kth, p.dYth, p.dPth, MC, D_, D_, nullptr, nullptr,
            p.W2, p.W2h, nullptr, p.W2Th, p.W1, p.W1Th, LR_);
        colsum2<<<dim3(32, 2), t8>>>(p.dYh, p.dPh, MC, p.b2, p.b1, LR_);
    }

    // final split weights for the 3-term retrieval path
    tconv<<<dim3(32, 32), t8>>>(p.W1, D_, D_, p.W1Th, p.W1Tl, nullptr);
    tconv<<<dim3(32, 32), t8>>>(p.W2, D_, D_, p.W2Th, p.W2Tl, nullptr);

    gemm_tc<EPI_Q,false,true,4,false><<<dim3(8, 128), 256, SMEM_3T4>>>(
        p.xh, p.xl, p.WQTh, p.WQTl, D_, D_, 0, nullptr, nullptr,
        nullptr, p.Qh, p.Ql, nullptr, nullptr, nullptr, 0.f);
    gemm_tc<EPI_SILU,false,true,4,false><<<dim3(8, 128), 256, SMEM_3T4>>>(
        p.Qh, p.Ql, p.W1Th, p.W1Tl, D_, D_, 0, p.b1, nullptr,
        nullptr, p.Hqh, p.Hql, nullptr, nullptr, nullptr, 0.f);
    gemm_tc<EPI_OUT,false,true,4,false><<<dim3(8, 128), 256, SMEM_3T4>>>(
        p.Hqh, p.Hql, p.W2Th, p.W2Tl, D_, D_, 0, p.b2, nullptr,
        out, nullptr, nullptr, nullptr, nullptr, nullptr, 0.f);
}

// round 15
// speedup vs baseline: 7.3542x; 1.0356x over previous
#include <cuda_runtime.h>
#include <cuda_bf16.h>
#include <cstdint>

constexpr int S_ = 2048, B_ = 8, D_ = 1024;
constexpr int TCH = 256, NCH = S_ / TCH, MC = TCH * B_, SB = S_ * B_;
constexpr float LR_ = 1e-3f;
constexpr size_t E1 = (size_t)SB * D_;
constexpr size_t MCD = (size_t)MC * D_;
constexpr size_t DD = (size_t)D_ * D_;
constexpr size_t ARENA_BYTES = 460ull << 20;
static __device__ __align__(1024) unsigned char g_arena[ARENA_BYTES];
static __device__ unsigned g_cnt = 0;
static __device__ unsigned g_gen = 0;
typedef __nv_bfloat16 bf;

constexpr int TILE_B = 128 * 80;          // 128 rows x 80B pitch
constexpr int SMEM_1T4 = 128 * 132 * 4;   // 67584
constexpr int SMEM_3T4 = 2 * 4 * TILE_B;  // 81920
constexpr int SMEM_2  = 128 * 68 * 4;     // 34816 (persistent kernel static smem)
constexpr int NCTA = 256;

__device__ __forceinline__ uint32_t s2u(const void* p) {
    uint32_t a;
    asm("{ .reg .u64 t; cvta.to.shared.u64 t, %1; cvt.u32.u64 %0, t; }" : "=r"(a) : "l"(p));
    return a;
}
__device__ __forceinline__ void cpa16(uint32_t dst, const void* src) {
    asm volatile("cp.async.cg.shared.global [%0], [%1], 16;" :: "r"(dst), "l"(src));
}
__device__ __forceinline__ void ldsm4(uint32_t* r, uint32_t a) {
    asm volatile("ldmatrix.sync.aligned.m8n8.x4.shared.b16 {%0,%1,%2,%3}, [%4];"
                 : "=r"(r[0]), "=r"(r[1]), "=r"(r[2]), "=r"(r[3]) : "r"(a));
}
__device__ __forceinline__ void mma16816(float* c, const uint32_t* a, const uint32_t* b) {
    asm volatile("mma.sync.aligned.m16n8k16.row.col.f32.bf16.bf16.f32 "
                 "{%0,%1,%2,%3}, {%4,%5,%6,%7}, {%8,%9}, {%0,%1,%2,%3};"
                 : "+f"(c[0]), "+f"(c[1]), "+f"(c[2]), "+f"(c[3])
                 : "r"(a[0]), "r"(a[1]), "r"(a[2]), "r"(a[3]), "r"(b[0]), "r"(b[1]));
}
__device__ __forceinline__ float sigf(float z) { return 1.f / (1.f + __expf(-z)); }
__device__ __forceinline__ void hilo(float v, bf& h, bf& l) {
    h = __float2bfloat16(v); l = __float2bfloat16(v - __bfloat162float(h));
}
enum { EPI_KV, EPI_FWD, EPI_DY, EPI_DPRE, EPI_UPD, EPI_SILU, EPI_OUT, EPI_Q };

// ---------------- grid barrier (all NCTA CTAs resident by launch_bounds) ----------------
__device__ __forceinline__ void gridbar() {
    __syncthreads();
    if (threadIdx.x == 0) {
        __threadfence();
        unsigned g = atomicAdd(&g_gen, 0u);
        if (atomicAdd(&g_cnt, 1u) == NCTA - 1) {
            g_cnt = 0;
            __threadfence();
            atomicExch(&g_gen, g + 1);
        } else {
            while (atomicAdd(&g_gen, 0u) == g) __nanosleep(64);
        }
    }
    __syncthreads();
}

// ---------------- NWN2 1-term GEMM as device function (128x64 tile, 128 thr) ------------
__device__ __forceinline__ void sload2(uint32_t sbuf, const bf* A, const bf* Bm,
                                       int m0, int n0, int K, int k0, int tid) {
#pragma unroll
    for (int idx = tid; idx < 768; idx += 128) {
        int t = idx, row0, off; const bf* g;
        if (t < 512) { g = A; row0 = m0; off = 0; }
        else         { t -= 512; g = Bm; row0 = n0; off = TILE_B; }
        int r = t >> 2, c = t & 3;
        cpa16(sbuf + off + r * 80 + c * 16, g + (size_t)(row0 + r) * K + k0 + c * 8);
    }
    asm volatile("cp.async.commit_group;" ::: "memory");
}

template <int EPI>
__device__ void scan_gemm(int m0, int n0,
    const bf* __restrict__ A, const bf* __restrict__ Bm, int K, int mtot,
    const float* __restrict__ bias, const float* __restrict__ aux,
    float* f0, bf* oh, bf* oth, float scale, char* smem)
{
    constexpr int PCH = 68, SSTR = TILE_B + 64 * 80;  // 15360
    const uint32_t sbase = s2u(smem);
    const int tid = threadIdx.x, lane = tid & 31, wid = tid >> 5;
    const int warp_m = wid & 1, warp_n = wid >> 1;

    float acc[4][4][4];
#pragma unroll
    for (int a = 0; a < 4; a++)
#pragma unroll
        for (int b = 0; b < 4; b++)
#pragma unroll
            for (int e = 0; e < 4; e++) acc[a][b][e] = 0.f;

    const int nst = K >> 5;
    sload2(sbase, A, Bm, m0, n0, K, 0, tid);
    for (int s = 0; s < nst; s++) {
        if (s + 1 < nst) {
            sload2(sbase + ((s + 1) & 1) * SSTR, A, Bm, m0, n0, K, (s + 1) * 32, tid);
            asm volatile("cp.async.wait_group 1;" ::: "memory");
        } else {
            asm volatile("cp.async.wait_group 0;" ::: "memory");
        }
        __syncthreads();
        const uint32_t st = sbase + (s & 1) * SSTR;
        const uint32_t sA = st, sB = st + TILE_B;
#pragma unroll
        for (int kc = 0; kc < 2; kc++) {
            uint32_t ra[4][4];
            const uint32_t a_off = kc * 32 + (lane >> 4) * 16;
            const int arow = warp_m * 64 + (lane & 15);
#pragma unroll
            for (int mt = 0; mt < 4; mt++)
                ldsm4(ra[mt], sA + (arow + mt * 16) * 80 + a_off);
            const int browoff = ((lane >> 4) << 3) + (lane & 7);
            const uint32_t b_off = kc * 32 + (((lane >> 3) & 1) * 16);
#pragma unroll
            for (int np = 0; np < 2; np++) {
                uint32_t r4[4];
                ldsm4(r4, sB + (warp_n * 32 + np * 16 + browoff) * 80 + b_off);
#pragma unroll
                for (int hf = 0; hf < 2; hf++) {
                    const int nt = 2 * np + hf;
                    uint32_t b2r[2] = { r4[2 * hf], r4[2 * hf + 1] };
#pragma unroll
                    for (int mt = 0; mt < 4; mt++)
                        mma16816(acc[mt][nt], ra[mt], b2r);
                }
            }
        }
        __syncthreads();
    }

    float* stg = reinterpret_cast<float*>(smem);
    {
        const int rb = warp_m * 64 + (lane >> 2);
        const int cb = warp_n * 32 + (lane & 3) * 2;
#pragma unroll
        for (int mt = 0; mt < 4; mt++)
#pragma unroll
            for (int nt = 0; nt < 4; nt++) {
                const int r = rb + mt * 16, c = cb + nt * 8;
                stg[r * PCH + c]           = acc[mt][nt][0];
                stg[r * PCH + c + 1]       = acc[mt][nt][1];
                stg[(r + 8) * PCH + c]     = acc[mt][nt][2];
                stg[(r + 8) * PCH + c + 1] = acc[mt][nt][3];
            }
    }
    __syncthreads();

    const int row = tid, m = m0 + row;
#pragma unroll 2
    for (int j = 0; j < 64; j += 4) {
        float4 v4 = *reinterpret_cast<float4*>(&stg[row * PCH + j]);
        float vv[4] = { v4.x, v4.y, v4.z, v4.w };
        float fin[4];
        const int nb = n0 + j;
#pragma unroll
        for (int e = 0; e < 4; e++) {
            const int n = nb + e;
            const float v = vv[e];
            if (EPI == EPI_FWD) {
                const float pre = v + bias[n];
                fin[e] = pre * sigf(pre);
            } else if (EPI == EPI_DY) {
                fin[e] = scale * (v + bias[n] - aux[(size_t)m * D_ + n]);
            } else if (EPI == EPI_DPRE) {
                const float z = aux[(size_t)m * D_ + n], sg = sigf(z);
                fin[e] = v * (sg * (1.f + z * (1.f - sg)));
            } else {  // EPI_UPD
                fin[e] = f0[(size_t)m * D_ + n] - scale * v;
            }
        }
        if (EPI == EPI_FWD) {
            float4 pr; pr.x = vv[0] + bias[nb]; pr.y = vv[1] + bias[nb+1];
            pr.z = vv[2] + bias[nb+2]; pr.w = vv[3] + bias[nb+3];
            *reinterpret_cast<float4*>(f0 + (size_t)m * D_ + nb) = pr;
        }
        if (EPI == EPI_UPD) {
            float4 w; w.x = fin[0]; w.y = fin[1]; w.z = fin[2]; w.w = fin[3];
            *reinterpret_cast<float4*>(f0 + (size_t)m * D_ + nb) = w;
        }
        if (oh) {
            bf h[4];
#pragma unroll
            for (int e = 0; e < 4; e++) h[e] = __float2bfloat16(fin[e]);
            *reinterpret_cast<uint2*>(oh + (size_t)m * D_ + nb) = *reinterpret_cast<uint2*>(h);
        }
        *reinterpret_cast<float4*>(&stg[row * PCH + j]) = make_float4(fin[0], fin[1], fin[2], fin[3]);
    }
    __syncthreads();
    {   // transposed bf16 output
        const int nrow = tid >> 1, mc0 = (tid & 1) * 64;
        const size_t gn = (size_t)(n0 + nrow);
#pragma unroll 2
        for (int j0 = 0; j0 < 64; j0 += 8) {
            union { bf b[8]; uint4 u; } H;
#pragma unroll
            for (int j = 0; j < 8; j++)
                H.b[j] = __float2bfloat16(stg[(mc0 + j0 + j) * PCH + nrow]);
            *reinterpret_cast<uint4*>(oth + gn * mtot + (m0 + mc0 + j0)) = H.u;
        }
    }
    __syncthreads();
}

struct SP_ {
    const bf *Kh, *Kta; const float* V;
    float *Pre, *W1, *W2, *b1, *b2;
    bf *H1h, *dYh, *dPh, *H1th, *dYth, *dPth;
    bf *W1Th, *W2Th, *W2h;
};

__global__ __launch_bounds__(128, 2) void scan_kernel(SP_ q, float c2) {
    __shared__ __align__(128) char smem[SMEM_2];
    const int r = blockIdx.x, tid = threadIdx.x;
    const int m0f = (r >> 4) * 128, n0f = (r & 15) * 64;   // FWD/DY/DPRE mapping
    const int z = r >> 7, rem = r & 127;
    const int m0u = (rem >> 4) * 128, n0u = (rem & 15) * 64;  // UPD mapping

    for (int c = 0; c < NCH; c++) {
        const bf* Kch = q.Kh + (size_t)c * MCD;
        const bf* Kth = q.Kta + (size_t)c * MCD;
        const float* Vc = q.V + (size_t)c * MCD;

        scan_gemm<EPI_FWD>(m0f, n0f, Kch, q.W1Th, D_, MC, q.b1, nullptr,
                           q.Pre, q.H1h, q.H1th, 0.f, smem);
        gridbar();
        scan_gemm<EPI_DY>(m0f, n0f, q.H1h, q.W2Th, D_, MC, q.b2, Vc,
                          nullptr, q.dYh, q.dYth, c2, smem);
        gridbar();
        scan_gemm<EPI_DPRE>(m0f, n0f, q.dYh, q.W2h, D_, MC, nullptr, q.Pre,
                            nullptr, q.dPh, q.dPth, 0.f, smem);
        gridbar();
        if (z == 0)
            scan_gemm<EPI_UPD>(m0u, n0u, q.H1th, q.dYth, MC, D_, nullptr, nullptr,
                               q.W2, q.W2h, q.W2Th, LR_, smem);
        else
            scan_gemm<EPI_UPD>(m0u, n0u, Kth, q.dPth, MC, D_, nullptr, nullptr,
                               q.W1, nullptr, q.W1Th, LR_, smem);
        {   // fused bias colsum: z=0 -> b2 from dY, z=1 -> b1 from dP (8 cols per CTA)
            const bf* src = z ? q.dPh : q.dYh;
            float* bp = z ? q.b1 : q.b2;
            const int col = rem * 8 + (tid & 7), r0 = tid >> 3;
            float s = 0.f;
            for (int rr = r0; rr < MC; rr += 16)
                s += __bfloat162float(src[(size_t)rr * D_ + col]);
            float* red = reinterpret_cast<float*>(smem);
            red[tid] = s;
            __syncthreads();
            if (tid < 8) {
                float t = 0.f;
#pragma unroll
                for (int i = 0; i < 16; i++) t += red[tid + 8 * i];
                bp[rem * 8 + tid] -= LR_ * t;
            }
        }
        gridbar();
    }
}

// ---------------- NWN4 GEMM (kv + retrieval) ----------------
template <bool SPLIT>
__device__ __forceinline__ void stage_load4(
    uint32_t sbuf, const bf* Ah, const bf* Al, const bf* Bh, const bf* Bl,
    int m0, int n0, int K, int k0, int tid)
{
    constexpr int TOT = (SPLIT ? 2 : 1) * 1024;
#pragma unroll
    for (int idx = tid; idx < TOT; idx += 256) {
        int t = idx, off, row0; const bf* g;
        if (t < 512)        { g = Ah; row0 = m0; off = 0; }
        else if (t < 1024)  { t -= 512; g = Bh; row0 = n0; off = TILE_B; }
        else if (t < 1536)  { t -= 1024; g = Al; row0 = m0; off = 2 * TILE_B; }
        else                { t -= 1536; g = Bl; row0 = n0; off = 3 * TILE_B; }
        int r = t >> 2, c = t & 3;
        cpa16(sbuf + off + r * 80 + c * 16, g + (size_t)(row0 + r) * K + k0 + c * 8);
    }
    asm volatile("cp.async.commit_group;" ::: "memory");
}

template <int EPI, bool SPLIT>
__global__ __launch_bounds__(256, 2) void gemm_tc(
    const bf* __restrict__ Ah, const bf* __restrict__ Al,
    const bf* __restrict__ Bh, const bf* __restrict__ Bl,
    int K, int Nout,
    const float* __restrict__ bias, float* f0, bf* oh, bf* __restrict__ ol)
{
    constexpr int PCH = 132;
    constexpr int SSTR = (SPLIT ? 4 : 2) * TILE_B;
    extern __shared__ __align__(128) char smem[];
    const uint32_t sbase = s2u(smem);
    const int tid = threadIdx.x, lane = tid & 31, wid = tid >> 5;
    const int warp_m = wid & 1, warp_n = wid >> 1;
    const int m0 = blockIdx.y * 128, n0 = blockIdx.x * 128;

    float acc[4][4][4];
#pragma unroll
    for (int a = 0; a < 4; a++)
#pragma unroll
        for (int b = 0; b < 4; b++)
#pragma unroll
            for (int e = 0; e < 4; e++) acc[a][b][e] = 0.f;

    const int nst = K >> 5;
    stage_load4<SPLIT>(sbase, Ah, Al, Bh, Bl, m0, n0, K, 0, tid);
    for (int s = 0; s < nst; s++) {
        if (s + 1 < nst) {
            stage_load4<SPLIT>(sbase + ((s + 1) & 1) * SSTR, Ah, Al, Bh, Bl,
                               m0, n0, K, (s + 1) * 32, tid);
            asm volatile("cp.async.wait_group 1;" ::: "memory");
        } else {
            asm volatile("cp.async.wait_group 0;" ::: "memory");
        }
        __syncthreads();
        const uint32_t st = sbase + (s & 1) * SSTR;
        const uint32_t sAh = st, sBh = st + TILE_B;
        const uint32_t sAl = st + 2 * TILE_B, sBl = st + 3 * TILE_B;
#pragma unroll
        for (int kc = 0; kc < 2; kc++) {
            uint32_t ra[4][4], rl[4][4];
            const uint32_t a_off = kc * 32 + (lane >> 4) * 16;
            const int arow = warp_m * 64 + (lane & 15);
#pragma unroll
            for (int mt = 0; mt < 4; mt++) {
                ldsm4(ra[mt], sAh + (arow + mt * 16) * 80 + a_off);
                if (SPLIT) ldsm4(rl[mt], sAl + (arow + mt * 16) * 80 + a_off);
            }
            const int browoff = ((lane >> 4) << 3) + (lane & 7);
            const uint32_t b_off = kc * 32 + (((lane >> 3) & 1) * 16);
#pragma unroll
            for (int np = 0; np < 2; np++) {
                uint32_t r4h[4], r4l[4];
                ldsm4(r4h, sBh + (warp_n * 32 + np * 16 + browoff) * 80 + b_off);
                if (SPLIT) ldsm4(r4l, sBl + (warp_n * 32 + np * 16 + browoff) * 80 + b_off);
#pragma unroll
                for (int hf = 0; hf < 2; hf++) {
                    const int nt = 2 * np + hf;
                    uint32_t bh2[2] = { r4h[2 * hf], r4h[2 * hf + 1] };
#pragma unroll
                    for (int mt = 0; mt < 4; mt++) {
                        mma16816(acc[mt][nt], ra[mt], bh2);
                        if (SPLIT) {
                            uint32_t bl2[2] = { r4l[2 * hf], r4l[2 * hf + 1] };
                            mma16816(acc[mt][nt], ra[mt], bl2);
                            mma16816(acc[mt][nt], rl[mt], bh2);
                        }
                    }
                }
            }
        }
        __syncthreads();
    }

    float* stg = reinterpret_cast<float*>(smem);
    {
        const int rb = warp_m * 64 + (lane >> 2);
        const int cb = warp_n * 32 + (lane & 3) * 2;
#pragma unroll
        for (int mt = 0; mt < 4; mt++)
#pragma unroll
            for (int nt = 0; nt < 4; nt++) {
                const int r = rb + mt * 16, c = cb + nt * 8;
                stg[r * PCH + c]           = acc[mt][nt][0];
                stg[r * PCH + c + 1]       = acc[mt][nt][1];
                stg[(r + 8) * PCH + c]     = acc[mt][nt][2];
                stg[(r + 8) * PCH + c + 1] = acc[mt][nt][3];
            }
    }
    __syncthreads();

    const int row = tid >> 1, col0 = (tid & 1) * 64;
    const int m = m0 + row;
#pragma unroll 2
    for (int j = 0; j < 64; j += 4) {
        float4 v4 = *reinterpret_cast<float4*>(&stg[row * PCH + col0 + j]);
        float vv[4] = { v4.x, v4.y, v4.z, v4.w };
        const int nb = n0 + col0 + j;
        if (EPI == EPI_KV) {
            const int bb = m >> 11, ss = m & (S_ - 1);
            const size_t base = (size_t)(ss * B_ + bb) * D_;
            if (nb < D_) {
                bf h[4];
#pragma unroll
                for (int e = 0; e < 4; e++) h[e] = __float2bfloat16(vv[e]);
                *reinterpret_cast<uint2*>(oh + base + nb) = *reinterpret_cast<uint2*>(h);
            } else {
                *reinterpret_cast<float4*>(f0 + base + nb - D_) = v4;
            }
            continue;
        }
        float fin[4];
#pragma unroll
        for (int e = 0; e < 4; e++) {
            const int n = nb + e;
            if (EPI == EPI_SILU) {
                const float pre = vv[e] + bias[n];
                fin[e] = pre * sigf(pre);
            } else if (EPI == EPI_OUT) {
                fin[e] = vv[e] + bias[n];
            } else {  // EPI_Q
                fin[e] = vv[e];
            }
        }
        if (EPI == EPI_OUT) {
            float4 w; w.x = fin[0]; w.y = fin[1]; w.z = fin[2]; w.w = fin[3];
            *reinterpret_cast<float4*>(f0 + (size_t)m * Nout + nb) = w;
        } else if (EPI != EPI_KV) {
            bf h[4], l[4];
#pragma unroll
            for (int e = 0; e < 4; e++) hilo(fin[e], h[e], l[e]);
            *reinterpret_cast<uint2*>(oh + (size_t)m * Nout + nb) = *reinterpret_cast<uint2*>(h);
            *reinterpret_cast<uint2*>(ol + (size_t)m * Nout + nb) = *reinterpret_cast<uint2*>(l);
        }
    }
}

__global__ __launch_bounds__(256) void conv_x(const float* __restrict__ in,
                                              bf* __restrict__ oh, bf* __restrict__ ol) {
    size_t i = (size_t)blockIdx.x * 1024 + threadIdx.x * 4;
    float4 v = *reinterpret_cast<const float4*>(in + i);
    bf h[4], l[4];
    hilo(v.x, h[0], l[0]); hilo(v.y, h[1], l[1]);
    hilo(v.z, h[2], l[2]); hilo(v.w, h[3], l[3]);
    *reinterpret_cast<uint2*>(oh + i) = *reinterpret_cast<uint2*>(h);
    *reinterpret_cast<uint2*>(ol + i) = *reinterpret_cast<uint2*>(l);
}
__global__ void tconv(const float* __restrict__ W, int R, int C,
                      bf* __restrict__ Th, bf* __restrict__ Tl, bf* __restrict__ Nh) {
    __shared__ float t[32][33];
    const int c0 = blockIdx.x * 32, r0 = blockIdx.y * 32, tx = threadIdx.x;
    for (int i = threadIdx.y; i < 32; i += 8) {
        float v = W[(size_t)(r0 + i) * C + c0 + tx];
        t[i][tx] = v;
        if (Nh) Nh[(size_t)(r0 + i) * C + c0 + tx] = __float2bfloat16(v);
    }
    __syncthreads();
    for (int i = threadIdx.y; i < 32; i += 8) {
        bf h, l; hilo(t[tx][i], h, l);
        Th[(size_t)(c0 + i) * R + r0 + tx] = h;
        if (Tl) Tl[(size_t)(c0 + i) * R + r0 + tx] = l;
    }
}
__global__ void tbf16b(const bf* __restrict__ ih, int R, int C, bf* __restrict__ oh) {
    ih += (size_t)blockIdx.z * MCD;
    oh += (size_t)blockIdx.z * MCD;
    __shared__ bf th[32][33];
    const int c0 = blockIdx.x * 32, r0 = blockIdx.y * 32, tx = threadIdx.x;
    for (int i = threadIdx.y; i < 32; i += 8)
        th[i][tx] = ih[(size_t)(r0 + i) * C + c0 + tx];
    __syncthreads();
    for (int i = threadIdx.y; i < 32; i += 8)
        oh[(size_t)(c0 + i) * R + r0 + tx] = th[tx][i];
}

struct P_ {
    bf *xh, *xl, *Kh, *Qh, *Ql, *Hqh, *Hql;
    float *V, *Pre, *W1, *W2, *b1, *b2;
    bf *H1h, *dYh, *dPh, *H1th, *dYth, *dPth, *Kta;
    bf *W1Th, *W1Tl, *W2Th, *W2Tl, *W2h, *WQTh, *WQTl, *WKVTh;
};
static P_ getp() {
    static P_ p = [] {
        P_ s{};
        unsigned char* a;
        cudaGetSymbolAddress((void**)&a, g_arena);
        auto al = [&](size_t bytes) { unsigned char* r = a; a += (bytes + 1023) & ~1023ull; return r; };
        s.xh=(bf*)al(E1*2); s.xl=(bf*)al(E1*2); s.Kh=(bf*)al(E1*2);
        s.Qh=(bf*)al(E1*2); s.Ql=(bf*)al(E1*2); s.Hqh=(bf*)al(E1*2); s.Hql=(bf*)al(E1*2);
        s.V=(float*)al(E1*4); s.Pre=(float*)al(MCD*4);
        s.W1=(float*)al(DD*4); s.W2=(float*)al(DD*4); s.b1=(float*)al(D_*4); s.b2=(float*)al(D_*4);
        s.H1h=(bf*)al(MCD*2); s.dYh=(bf*)al(MCD*2); s.dPh=(bf*)al(MCD*2);
        s.H1th=(bf*)al(MCD*2); s.dYth=(bf*)al(MCD*2); s.dPth=(bf*)al(MCD*2);
        s.Kta=(bf*)al(NCH*MCD*2);
        s.W1Th=(bf*)al(DD*2); s.W1Tl=(bf*)al(DD*2); s.W2Th=(bf*)al(DD*2); s.W2Tl=(bf*)al(DD*2);
        s.W2h=(bf*)al(DD*2); s.WQTh=(bf*)al(DD*2); s.WQTl=(bf*)al(DD*2);
        s.WKVTh=(bf*)al(DD*4);
        cudaFuncSetAttribute(gemm_tc<EPI_KV,false>,  cudaFuncAttributeMaxDynamicSharedMemorySize, SMEM_1T4);
        cudaFuncSetAttribute(gemm_tc<EPI_Q,true>,    cudaFuncAttributeMaxDynamicSharedMemorySize, SMEM_3T4);
        cudaFuncSetAttribute(gemm_tc<EPI_SILU,true>, cudaFuncAttributeMaxDynamicSharedMemorySize, SMEM_3T4);
        cudaFuncSetAttribute(gemm_tc<EPI_OUT,true>,  cudaFuncAttributeMaxDynamicSharedMemorySize, SMEM_3T4);
        return s;
    }();
    return p;
}

extern "C" void kernel_launch(void* const* d_in, const int* in_sizes, int n_in,
                              void* d_out, int out_size)
{
    const float* x   = (const float*)d_in[0];
    const float* WQ  = (const float*)d_in[1];
    const float* WKV = (const float*)d_in[2];
    const float* W1i = (const float*)d_in[3];
    const float* b1i = (const float*)d_in[4];
    const float* W2i = (const float*)d_in[5];
    const float* b2i = (const float*)d_in[6];
    float* out = (float*)d_out;
    P_ p = getp();
    const dim3 t8(32, 8);
    const float c2 = 2.f / (float)(B_ * D_);

    cudaMemcpyAsync(p.W1, W1i, DD * 4, cudaMemcpyDeviceToDevice);
    cudaMemcpyAsync(p.W2, W2i, DD * 4, cudaMemcpyDeviceToDevice);
    cudaMemcpyAsync(p.b1, b1i, D_ * 4, cudaMemcpyDeviceToDevice);
    cudaMemcpyAsync(p.b2, b2i, D_ * 4, cudaMemcpyDeviceToDevice);

    conv_x<<<E1 / 1024, 256>>>(x, p.xh, p.xl);
    tconv<<<dim3(32, 32), t8>>>(WQ, D_, D_, p.WQTh, p.WQTl, nullptr);
    tconv<<<dim3(64, 32), t8>>>(WKV, D_, 2 * D_, p.WKVTh, nullptr, nullptr);
    tconv<<<dim3(32, 32), t8>>>(p.W1, D_, D_, p.W1Th, nullptr, nullptr);
    tconv<<<dim3(32, 32), t8>>>(p.W2, D_, D_, p.W2Th, nullptr, p.W2h);

    gemm_tc<EPI_KV,false><<<dim3(16, 128), 256, SMEM_1T4>>>(
        p.xh, nullptr, p.WKVTh, nullptr, D_, 2 * D_, nullptr, p.V, p.Kh, nullptr);

    tbf16b<<<dim3(32, 64, NCH), t8>>>(p.Kh, MC, D_, p.Kta);

    SP_ sp{ p.Kh, p.Kta, p.V, p.Pre, p.W1, p.W2, p.b1, p.b2,
            p.H1h, p.dYh, p.dPh, p.H1th, p.dYth, p.dPth,
            p.W1Th, p.W2Th, p.W2h };
    scan_kernel<<<NCTA, 128>>>(sp, c2);

    tconv<<<dim3(32, 32), t8>>>(p.W1, D_, D_, p.W1Th, p.W1Tl, nullptr);
    tconv<<<dim3(32, 32), t8>>>(p.W2, D_, D_, p.W2Th, p.W2Tl, nullptr);

    gemm_tc<EPI_Q,true><<<dim3(8, 128), 256, SMEM_3T4>>>(
        p.xh, p.xl, p.WQTh, p.WQTl, D_, D_, nullptr, nullptr, p.Qh, p.Ql);
    gemm_tc<EPI_SILU,true><<<dim3(8, 128), 256, SMEM_3T4>>>(
        p.Qh, p.Ql, p.W1Th, p.W1Tl, D_, D_, p.b1, nullptr, p.Hqh, p.Hql);
    gemm_tc<EPI_OUT,true><<<dim3(8, 128), 256, SMEM_3T4>>>(
        p.Hqh, p.Hql, p.W2Th, p.W2Tl, D_, D_, p.b2, out, nullptr, nullptr);
}